// round 2
// baseline (speedup 1.0000x reference)
#include <cuda_runtime.h>
#include <cuda_bf16.h>

// Problem constants (fixed by the reference): B=2, T=4096, C=64, H=4, Dh=16
#define B_SZ 2
#define T_SZ 4096
#define C_SZ 64
#define H_SZ 4
#define DH 16
#define BH (B_SZ * H_SZ)          // 8
#define ROWS (B_SZ * T_SZ)        // 8192

// -------- scratch (allocation-free rule: __device__ globals) --------
__device__ float g_q[BH * T_SZ * DH];   // [bh][t][d]
__device__ float g_k[BH * T_SZ * DH];
__device__ float g_v[BH * T_SZ * DH];
__device__ float g_y[ROWS * C_SZ];      // [b*T + t][c]

// ==================== Kernel 1: fused QKV projection ====================
// qkv[row, c] = dot(x[row, :], w_attn[c, :]) + b_attn[c], scattered into
// head-major q/k/v scratch.  blockDim = 192 (one thread per output col),
// 16 rows per block.  wT staged in smem (48KB, conflict-free: [k][c]).
__global__ void __launch_bounds__(192) qkv_kernel(
    const float* __restrict__ x, const float* __restrict__ w,
    const float* __restrict__ b)
{
    __shared__ float sw[64 * 192];  // sw[k*192 + c] = w[c*64 + k]
    const int t = threadIdx.x;      // 0..191 = output column

    for (int idx = t; idx < 64 * 192; idx += 192) {
        int k = idx / 192, c = idx % 192;
        sw[idx] = w[c * 64 + k];
    }
    __syncthreads();

    const int row0 = blockIdx.x * 16;
    const float* xr = x + row0 * 64;
    const float bias = b[t];

    float acc[16];
#pragma unroll
    for (int r = 0; r < 16; r++) acc[r] = bias;

#pragma unroll 4
    for (int k = 0; k < 64; k++) {
        const float wv = sw[k * 192 + t];
#pragma unroll
        for (int r = 0; r < 16; r++)
            acc[r] += __ldg(&xr[r * 64 + k]) * wv;
    }

    // scatter: c -> (which in {q,k,v}, head, d)
    const int which = t >> 6;          // 0,1,2
    const int cc    = t & 63;
    const int h     = cc >> 4;
    const int d     = cc & 15;
    float* dst = (which == 0) ? g_q : (which == 1) ? g_k : g_v;

#pragma unroll
    for (int r = 0; r < 16; r++) {
        const int row = row0 + r;
        const int bi  = row >> 12;       // /T_SZ
        const int ti  = row & 4095;
        dst[((bi * H_SZ + h) * T_SZ + ti) * DH + d] = acc[r];
    }
}

// ==================== Kernel 2: flash attention ====================
// One thread per query (Dh=16 accs in regs), K/V tiles of 128 keys in smem,
// online softmax with one rescale per 16-key chunk. Scale folded into q.
#define TK 128
#define QB 128

__global__ void __launch_bounds__(QB) attn_kernel()
{
    __shared__ float sk[TK * DH];
    __shared__ float sv[TK * DH];

    const int bh = blockIdx.y;                  // 0..7
    const int q0 = blockIdx.x * QB;
    const int t  = threadIdx.x;

    // load q row, fold in softmax scale 1/sqrt(16) = 0.25
    float q[16];
    {
        const float4* qp = (const float4*)(g_q + (bh * T_SZ + q0 + t) * DH);
#pragma unroll
        for (int i = 0; i < 4; i++) {
            float4 f = qp[i];
            q[i * 4 + 0] = f.x * 0.25f;
            q[i * 4 + 1] = f.y * 0.25f;
            q[i * 4 + 2] = f.z * 0.25f;
            q[i * 4 + 3] = f.w * 0.25f;
        }
    }

    float m = -1e30f, l = 0.0f;
    float acc[16];
#pragma unroll
    for (int d = 0; d < 16; d++) acc[d] = 0.0f;

    const float4* kb = (const float4*)(g_k + bh * T_SZ * DH);
    const float4* vb = (const float4*)(g_v + bh * T_SZ * DH);

    for (int kt = 0; kt < T_SZ; kt += TK) {
        __syncthreads();   // previous tile fully consumed
        {
            const float4* ks4 = kb + kt * (DH / 4);
            const float4* vs4 = vb + kt * (DH / 4);
            float4* sk4 = (float4*)sk;
            float4* sv4 = (float4*)sv;
#pragma unroll
            for (int i = 0; i < 4; i++) {
                sk4[t + i * 128] = ks4[t + i * 128];
                sv4[t + i * 128] = vs4[t + i * 128];
            }
        }
        __syncthreads();

#pragma unroll 1
        for (int c0 = 0; c0 < TK; c0 += 16) {
            float s[16];
#pragma unroll
            for (int j = 0; j < 16; j++) {
                const float4* kr = (const float4*)(sk + (c0 + j) * DH);
                float4 k0 = kr[0], k1 = kr[1], k2 = kr[2], k3 = kr[3];
                float sum;
                sum  = q[0]  * k0.x;  sum += q[1]  * k0.y;
                sum += q[2]  * k0.z;  sum += q[3]  * k0.w;
                sum += q[4]  * k1.x;  sum += q[5]  * k1.y;
                sum += q[6]  * k1.z;  sum += q[7]  * k1.w;
                sum += q[8]  * k2.x;  sum += q[9]  * k2.y;
                sum += q[10] * k2.z;  sum += q[11] * k2.w;
                sum += q[12] * k3.x;  sum += q[13] * k3.y;
                sum += q[14] * k3.z;  sum += q[15] * k3.w;
                s[j] = sum;
            }
            float cm = s[0];
#pragma unroll
            for (int j = 1; j < 16; j++) cm = fmaxf(cm, s[j]);
            const float mnew = fmaxf(m, cm);
            const float corr = __expf(m - mnew);
            l *= corr;
#pragma unroll
            for (int d = 0; d < 16; d++) acc[d] *= corr;

#pragma unroll
            for (int j = 0; j < 16; j++) {
                const float p = __expf(s[j] - mnew);
                l += p;
                const float4* vr = (const float4*)(sv + (c0 + j) * DH);
                float4 v0 = vr[0], v1 = vr[1], v2 = vr[2], v3 = vr[3];
                acc[0]  += p * v0.x;  acc[1]  += p * v0.y;
                acc[2]  += p * v0.z;  acc[3]  += p * v0.w;
                acc[4]  += p * v1.x;  acc[5]  += p * v1.y;
                acc[6]  += p * v1.z;  acc[7]  += p * v1.w;
                acc[8]  += p * v2.x;  acc[9]  += p * v2.y;
                acc[10] += p * v2.z;  acc[11] += p * v2.w;
                acc[12] += p * v3.x;  acc[13] += p * v3.y;
                acc[14] += p * v3.z;  acc[15] += p * v3.w;
            }
            m = mnew;
        }
    }

    const float inv = 1.0f / l;
    const int h  = bh & 3;
    const int bi = bh >> 2;
    float4* yp = (float4*)(g_y + (bi * T_SZ + q0 + t) * C_SZ + h * DH);
#pragma unroll
    for (int i = 0; i < 4; i++) {
        float4 f;
        f.x = acc[i * 4 + 0] * inv;
        f.y = acc[i * 4 + 1] * inv;
        f.z = acc[i * 4 + 2] * inv;
        f.w = acc[i * 4 + 3] * inv;
        yp[i] = f;
    }
}

// ==================== Kernel 3: output projection ====================
// out[row, c] = dot(y[row,:], w_proj[c,:]) + b_proj[c]
// blockDim = 256: col = t&63, row-group = t>>6 (4 groups x 16 rows = 64 rows/block)
__global__ void __launch_bounds__(256) proj_kernel(
    const float* __restrict__ w, const float* __restrict__ b,
    float* __restrict__ out)
{
    __shared__ float sw[64 * 64];   // sw[k*64 + c] = w[c*64 + k]
    const int t = threadIdx.x;
    for (int idx = t; idx < 64 * 64; idx += 256) {
        int k = idx >> 6, c = idx & 63;
        sw[idx] = w[c * 64 + k];
    }
    __syncthreads();

    const int col  = t & 63;
    const int rg   = t >> 6;
    const int row0 = blockIdx.x * 64 + rg * 16;
    const float bias = b[col];

    float acc[16];
#pragma unroll
    for (int r = 0; r < 16; r++) acc[r] = bias;

    const float* xr = g_y + row0 * 64;
#pragma unroll 4
    for (int k = 0; k < 64; k++) {
        const float wv = sw[k * 64 + col];
#pragma unroll
        for (int r = 0; r < 16; r++)
            acc[r] += xr[r * 64 + k] * wv;
    }

#pragma unroll
    for (int r = 0; r < 16; r++)
        out[(row0 + r) * 64 + col] = acc[r];
}

// ==================== launch ====================
extern "C" void kernel_launch(void* const* d_in, const int* in_sizes, int n_in,
                              void* d_out, int out_size)
{
    const float* x      = (const float*)d_in[0];  // [2,4096,64]
    const float* w_attn = (const float*)d_in[1];  // [192,64]
    const float* b_attn = (const float*)d_in[2];  // [192]
    const float* w_proj = (const float*)d_in[3];  // [64,64]
    const float* b_proj = (const float*)d_in[4];  // [64]
    float* out = (float*)d_out;                   // [2,4096,64]

    qkv_kernel<<<ROWS / 16, 192>>>(x, w_attn, b_attn);

    dim3 ag(T_SZ / QB, BH);   // (32, 8)
    attn_kernel<<<ag, QB>>>();

    proj_kernel<<<ROWS / 64, 256>>>(w_proj, b_proj, out);
}

// round 5
// speedup vs baseline: 1.3612x; 1.3612x over previous
#include <cuda_runtime.h>
#include <cuda_bf16.h>

// Problem constants: B=2, T=4096, C=64, H=4, Dh=16
#define B_SZ 2
#define T_SZ 4096
#define C_SZ 64
#define H_SZ 4
#define DH 16
#define BH (B_SZ * H_SZ)          // 8
#define ROWS (B_SZ * T_SZ)        // 8192

// log2(e) * softmax scale (1/sqrt(16)) folded into q once
#define QSCALE 0.360673760222241f   // 0.25 * 1.4426950408889634

// -------- scratch (allocation-free rule: __device__ globals) --------
__device__ float g_q[BH * T_SZ * DH];   // [bh][t][d]
__device__ float g_k[BH * T_SZ * DH];
__device__ float g_v[BH * T_SZ * DH];
__device__ float g_y[ROWS * C_SZ];      // [b*T + t][c]

// ---------------- f32x2 packed-math helpers ----------------
__device__ __forceinline__ unsigned long long pack2(float lo, float hi) {
    unsigned long long r;
    asm("mov.b64 %0, {%1, %2};" : "=l"(r) : "f"(lo), "f"(hi));
    return r;
}
__device__ __forceinline__ void unpack2(unsigned long long v, float& lo, float& hi) {
    asm("mov.b64 {%0, %1}, %2;" : "=f"(lo), "=f"(hi) : "l"(v));
}
__device__ __forceinline__ unsigned long long fma2(unsigned long long a,
                                                   unsigned long long b,
                                                   unsigned long long c) {
    unsigned long long d;
    asm("fma.rn.f32x2 %0, %1, %2, %3;" : "=l"(d) : "l"(a), "l"(b), "l"(c));
    return d;
}
__device__ __forceinline__ unsigned long long mul2(unsigned long long a,
                                                   unsigned long long b) {
    unsigned long long d;
    asm("mul.rn.f32x2 %0, %1, %2;" : "=l"(d) : "l"(a), "l"(b));
    return d;
}
__device__ __forceinline__ unsigned long long add2(unsigned long long a,
                                                   unsigned long long b) {
    unsigned long long d;
    asm("add.rn.f32x2 %0, %1, %2;" : "=l"(d) : "l"(a), "l"(b));
    return d;
}
__device__ __forceinline__ float ex2f(float x) {
    float y;
    asm("ex2.approx.ftz.f32 %0, %1;" : "=f"(y) : "f"(x));
    return y;
}

// ==================== Kernel 1: fused QKV projection ====================
// 192 threads (one per output col), 16 rows per block. Weights transposed
// into smem as float4 quads (conflict-free LDS.128); x read as broadcast
// LDG.128 (L1-resident).
__global__ void __launch_bounds__(192) qkv_kernel(
    const float* __restrict__ x, const float* __restrict__ w,
    const float* __restrict__ b)
{
    __shared__ float4 sw4[16 * 192];   // sw4[k4*192 + c] = w[c][4k4..4k4+3]  (48KB)
    const int t = threadIdx.x;

    const float4* w4 = (const float4*)w;     // w4[c*16 + k4]
    for (int idx = t; idx < 192 * 16; idx += 192) {
        int c = idx >> 4, k4 = idx & 15;
        sw4[k4 * 192 + c] = w4[idx];
    }
    __syncthreads();

    const int row0 = blockIdx.x * 16;
    const float4* x4 = (const float4*)x + row0 * 16;   // 16 rows x 16 float4
    const float bias = b[t];

    float acc[16];
#pragma unroll
    for (int r = 0; r < 16; r++) acc[r] = bias;

#pragma unroll 4
    for (int k4 = 0; k4 < 16; k4++) {
        const float4 wv = sw4[k4 * 192 + t];
#pragma unroll
        for (int r = 0; r < 16; r++) {
            const float4 xv = __ldg(&x4[r * 16 + k4]);   // warp-uniform broadcast
            acc[r] += xv.x * wv.x;
            acc[r] += xv.y * wv.y;
            acc[r] += xv.z * wv.z;
            acc[r] += xv.w * wv.w;
        }
    }

    // scatter into head-major q/k/v; q pre-scaled by 0.25*log2(e)
    const int which = t >> 6;          // 0=q, 1=k, 2=v
    const int cc    = t & 63;
    const int h     = cc >> 4;
    const int d     = cc & 15;
    float* dst = (which == 0) ? g_q : (which == 1) ? g_k : g_v;
    const float mulf = (which == 0) ? QSCALE : 1.0f;

#pragma unroll
    for (int r = 0; r < 16; r++) {
        const int row = row0 + r;
        const int bi  = row >> 12;
        const int ti  = row & 4095;
        dst[((bi * H_SZ + h) * T_SZ + ti) * DH + d] = acc[r] * mulf;
    }
}

// ==================== Kernel 2: flash attention (f32x2) ====================
// One warp per block, one thread per query. Softmax in log2 domain
// (scale*log2e folded into q), packed dual-lane FMA for QK and PV.
#define TK 128
#define QB 32

__global__ void __launch_bounds__(QB) attn_kernel()
{
    __shared__ float sk[TK * DH];
    __shared__ float sv[TK * DH];

    const int bh = blockIdx.y;                  // 0..7
    const int q0 = blockIdx.x * QB;
    const int t  = threadIdx.x;

    // q (already scaled), packed into 8 f32x2
    unsigned long long q2[8];
    {
        const float4* qp = (const float4*)(g_q + (bh * T_SZ + q0 + t) * DH);
#pragma unroll
        for (int i = 0; i < 4; i++) {
            float4 f = qp[i];
            q2[2 * i]     = pack2(f.x, f.y);
            q2[2 * i + 1] = pack2(f.z, f.w);
        }
    }

    float m = -1e30f, l = 0.0f;
    unsigned long long acc2[8];
#pragma unroll
    for (int i = 0; i < 8; i++) acc2[i] = 0ull;   // (0.0f, 0.0f)

    const float4* kb = (const float4*)(g_k + bh * T_SZ * DH);
    const float4* vb = (const float4*)(g_v + bh * T_SZ * DH);

    for (int kt = 0; kt < T_SZ; kt += TK) {
        __syncwarp();
        {
            const float4* ks4 = kb + kt * 4;
            const float4* vs4 = vb + kt * 4;
            float4* sk4 = (float4*)sk;
            float4* sv4 = (float4*)sv;
#pragma unroll
            for (int i = 0; i < 16; i++) {      // 512 float4 each, 32 lanes
                sk4[t + i * 32] = ks4[t + i * 32];
                sv4[t + i * 32] = vs4[t + i * 32];
            }
        }
        __syncwarp();

#pragma unroll 1
        for (int c0 = 0; c0 < TK; c0 += 16) {
            float s[16];
#pragma unroll
            for (int j = 0; j < 16; j++) {
                const ulonglong2* kr = (const ulonglong2*)(sk + (c0 + j) * DH);
                ulonglong2 kA = kr[0], kB = kr[1], kC = kr[2], kD = kr[3];
                unsigned long long a = mul2(q2[0], kA.x);
                unsigned long long c = mul2(q2[1], kA.y);
                a = fma2(q2[2], kB.x, a);
                c = fma2(q2[3], kB.y, c);
                a = fma2(q2[4], kC.x, a);
                c = fma2(q2[5], kC.y, c);
                a = fma2(q2[6], kD.x, a);
                c = fma2(q2[7], kD.y, c);
                a = add2(a, c);
                float lo, hi;
                unpack2(a, lo, hi);
                s[j] = lo + hi;                 // score in log2 units
            }

            // chunk max (tree)
            float m0 = fmaxf(s[0], s[1]),   m1 = fmaxf(s[2], s[3]);
            float m2 = fmaxf(s[4], s[5]),   m3 = fmaxf(s[6], s[7]);
            float m4 = fmaxf(s[8], s[9]),   m5 = fmaxf(s[10], s[11]);
            float m6 = fmaxf(s[12], s[13]), m7 = fmaxf(s[14], s[15]);
            m0 = fmaxf(m0, m1); m2 = fmaxf(m2, m3);
            m4 = fmaxf(m4, m5); m6 = fmaxf(m6, m7);
            m0 = fmaxf(m0, m2); m4 = fmaxf(m4, m6);
            const float mnew = fmaxf(m, fmaxf(m0, m4));

            const float corr = ex2f(m - mnew);
            l *= corr;
            const unsigned long long c2 = pack2(corr, corr);
#pragma unroll
            for (int i = 0; i < 8; i++) acc2[i] = mul2(acc2[i], c2);

#pragma unroll
            for (int j = 0; j < 16; j++) {
                const float p = ex2f(s[j] - mnew);
                l += p;
                const unsigned long long pp = pack2(p, p);
                const ulonglong2* vr = (const ulonglong2*)(sv + (c0 + j) * DH);
                ulonglong2 vA = vr[0], vB = vr[1], vC = vr[2], vD = vr[3];
                acc2[0] = fma2(pp, vA.x, acc2[0]);
                acc2[1] = fma2(pp, vA.y, acc2[1]);
                acc2[2] = fma2(pp, vB.x, acc2[2]);
                acc2[3] = fma2(pp, vB.y, acc2[3]);
                acc2[4] = fma2(pp, vC.x, acc2[4]);
                acc2[5] = fma2(pp, vC.y, acc2[5]);
                acc2[6] = fma2(pp, vD.x, acc2[6]);
                acc2[7] = fma2(pp, vD.y, acc2[7]);
            }
            m = mnew;
        }
    }

    const float inv = 1.0f / l;
    const int h  = bh & 3;
    const int bi = bh >> 2;
    float4* yp = (float4*)(g_y + (bi * T_SZ + q0 + t) * C_SZ + h * DH);
#pragma unroll
    for (int i = 0; i < 4; i++) {
        float lo0, hi0, lo1, hi1;
        unpack2(acc2[2 * i], lo0, hi0);
        unpack2(acc2[2 * i + 1], lo1, hi1);
        float4 f;
        f.x = lo0 * inv; f.y = hi0 * inv;
        f.z = lo1 * inv; f.w = hi1 * inv;
        yp[i] = f;
    }
}

// ==================== Kernel 3: output projection ====================
// 256 threads: col = t&63, 4 row-groups x 16 rows = 64 rows per block.
__global__ void __launch_bounds__(256) proj_kernel(
    const float* __restrict__ w, const float* __restrict__ b,
    float* __restrict__ out)
{
    __shared__ float4 sw4[16 * 64];    // sw4[k4*64 + c] = w[c][4k4..]  (16KB)
    const int t = threadIdx.x;

    const float4* w4 = (const float4*)w;   // w4[c*16 + k4]
    for (int idx = t; idx < 64 * 16; idx += 256) {
        int c = idx >> 4, k4 = idx & 15;
        sw4[k4 * 64 + c] = w4[idx];
    }
    __syncthreads();

    const int col  = t & 63;
    const int rg   = t >> 6;
    const int row0 = blockIdx.x * 64 + rg * 16;
    const float bias = b[col];

    float acc[16];
#pragma unroll
    for (int r = 0; r < 16; r++) acc[r] = bias;

    const float4* x4 = (const float4*)g_y + row0 * 16;
#pragma unroll 4
    for (int k4 = 0; k4 < 16; k4++) {
        const float4 wv = sw4[k4 * 64 + col];
#pragma unroll
        for (int r = 0; r < 16; r++) {
            const float4 xv = __ldg(&x4[r * 16 + k4]);
            acc[r] += xv.x * wv.x;
            acc[r] += xv.y * wv.y;
            acc[r] += xv.z * wv.z;
            acc[r] += xv.w * wv.w;
        }
    }

#pragma unroll
    for (int r = 0; r < 16; r++)
        out[(row0 + r) * 64 + col] = acc[r];
}

// ==================== launch ====================
extern "C" void kernel_launch(void* const* d_in, const int* in_sizes, int n_in,
                              void* d_out, int out_size)
{
    const float* x      = (const float*)d_in[0];  // [2,4096,64]
    const float* w_attn = (const float*)d_in[1];  // [192,64]
    const float* b_attn = (const float*)d_in[2];  // [192]
    const float* w_proj = (const float*)d_in[3];  // [64,64]
    const float* b_proj = (const float*)d_in[4];  // [64]
    float* out = (float*)d_out;                   // [2,4096,64]

    qkv_kernel<<<ROWS / 16, 192>>>(x, w_attn, b_attn);

    dim3 ag(T_SZ / QB, BH);   // (128, 8) = 1024 one-warp blocks
    attn_kernel<<<ag, QB>>>();

    proj_kernel<<<ROWS / 64, 256>>>(w_proj, b_proj, out);
}

// round 6
// speedup vs baseline: 1.4687x; 1.0790x over previous
#include <cuda_runtime.h>
#include <cuda_bf16.h>

// Problem constants: B=2, T=4096, C=64, H=4, Dh=16
#define B_SZ 2
#define T_SZ 4096
#define C_SZ 64
#define H_SZ 4
#define DH 16
#define BH (B_SZ * H_SZ)          // 8
#define ROWS (B_SZ * T_SZ)        // 8192

// log2(e) * softmax scale (1/sqrt(16)) folded into q once
#define QSCALE 0.360673760222241f   // 0.25 * 1.4426950408889634

#define NSPLIT 4
#define KSPAN (T_SZ / NSPLIT)      // 1024 keys per split
#define TK 128
#define QB 128

// -------- scratch (allocation-free rule: __device__ globals) --------
__device__ float g_q[BH * T_SZ * DH];            // [bh][t][d] (pre-scaled)
__device__ float g_k[BH * T_SZ * DH];
__device__ float g_v[BH * T_SZ * DH];
__device__ float g_y[ROWS * C_SZ];               // [b*T + t][c]
__device__ float g_pm[NSPLIT][BH * T_SZ];        // partial max (log2 units)
__device__ float g_pl[NSPLIT][BH * T_SZ];        // partial sum
__device__ float g_pacc[NSPLIT][BH * T_SZ * DH]; // partial unnormalized out

// ---------------- f32x2 packed-math helpers ----------------
__device__ __forceinline__ unsigned long long pack2(float lo, float hi) {
    unsigned long long r;
    asm("mov.b64 %0, {%1, %2};" : "=l"(r) : "f"(lo), "f"(hi));
    return r;
}
__device__ __forceinline__ void unpack2(unsigned long long v, float& lo, float& hi) {
    asm("mov.b64 {%0, %1}, %2;" : "=f"(lo), "=f"(hi) : "l"(v));
}
__device__ __forceinline__ unsigned long long fma2(unsigned long long a,
                                                   unsigned long long b,
                                                   unsigned long long c) {
    unsigned long long d;
    asm("fma.rn.f32x2 %0, %1, %2, %3;" : "=l"(d) : "l"(a), "l"(b), "l"(c));
    return d;
}
__device__ __forceinline__ unsigned long long mul2(unsigned long long a,
                                                   unsigned long long b) {
    unsigned long long d;
    asm("mul.rn.f32x2 %0, %1, %2;" : "=l"(d) : "l"(a), "l"(b));
    return d;
}
__device__ __forceinline__ unsigned long long add2(unsigned long long a,
                                                   unsigned long long b) {
    unsigned long long d;
    asm("add.rn.f32x2 %0, %1, %2;" : "=l"(d) : "l"(a), "l"(b));
    return d;
}
__device__ __forceinline__ float ex2f(float x) {
    float y;
    asm("ex2.approx.ftz.f32 %0, %1;" : "=f"(y) : "f"(x));
    return y;
}

// ==================== Kernel 1: fused QKV projection (f32x2) ============
__global__ void __launch_bounds__(192) qkv_kernel(
    const float* __restrict__ x, const float* __restrict__ w,
    const float* __restrict__ b)
{
    __shared__ float4 sw4[16 * 192];   // sw4[k4*192 + c] = w[c][4k4..4k4+3]
    const int t = threadIdx.x;

    const float4* w4 = (const float4*)w;     // w4[c*16 + k4]
    for (int idx = t; idx < 192 * 16; idx += 192) {
        int c = idx >> 4, k4 = idx & 15;
        sw4[k4 * 192 + c] = w4[idx];
    }
    __syncthreads();

    const int row0 = blockIdx.x * 16;
    const float4* x4 = (const float4*)x + row0 * 16;
    const float bias = b[t];

    unsigned long long acc2[16];
#pragma unroll
    for (int r = 0; r < 16; r++) acc2[r] = 0ull;

#pragma unroll 4
    for (int k4 = 0; k4 < 16; k4++) {
        const float4 wv = sw4[k4 * 192 + t];
        const unsigned long long w01 = pack2(wv.x, wv.y);
        const unsigned long long w23 = pack2(wv.z, wv.w);
#pragma unroll
        for (int r = 0; r < 16; r++) {
            const float4 xv = __ldg(&x4[r * 16 + k4]);   // warp-uniform broadcast
            acc2[r] = fma2(pack2(xv.x, xv.y), w01, acc2[r]);
            acc2[r] = fma2(pack2(xv.z, xv.w), w23, acc2[r]);
        }
    }

    // scatter into head-major q/k/v; q pre-scaled by 0.25*log2(e)
    const int which = t >> 6;          // 0=q, 1=k, 2=v
    const int cc    = t & 63;
    const int h     = cc >> 4;
    const int d     = cc & 15;
    float* dst = (which == 0) ? g_q : (which == 1) ? g_k : g_v;
    const float mulf = (which == 0) ? QSCALE : 1.0f;

#pragma unroll
    for (int r = 0; r < 16; r++) {
        const int row = row0 + r;
        const int bi  = row >> 12;
        const int ti  = row & 4095;
        float lo, hi;
        unpack2(acc2[r], lo, hi);
        dst[((bi * H_SZ + h) * T_SZ + ti) * DH + d] = (lo + hi + bias) * mulf;
    }
}

// ============ Kernel 2: split-K flash attention (f32x2, partials) =======
// Grid (T/QB, BH, NSPLIT), 128 threads (4 warps) per block. One thread per
// query; all warps share one K/V tile in smem (co-op loaded). Each block
// covers KSPAN keys and emits partial (m, l, acc16) per query.
__global__ void __launch_bounds__(QB, 5) attn_kernel()
{
    __shared__ float sk[TK * DH];
    __shared__ float sv[TK * DH];

    const int bh = blockIdx.y;
    const int q0 = blockIdx.x * QB;
    const int sp = blockIdx.z;
    const int t  = threadIdx.x;
    const int qi = bh * T_SZ + q0 + t;       // global (bh, query) index

    // q (already scaled to log2 domain), packed into 8 f32x2
    unsigned long long q2[8];
    {
        const float4* qp = (const float4*)(g_q + qi * DH);
#pragma unroll
        for (int i = 0; i < 4; i++) {
            float4 f = qp[i];
            q2[2 * i]     = pack2(f.x, f.y);
            q2[2 * i + 1] = pack2(f.z, f.w);
        }
    }

    float m = -1e30f, l = 0.0f;
    unsigned long long acc2[8];
#pragma unroll
    for (int i = 0; i < 8; i++) acc2[i] = 0ull;

    const float4* kb = (const float4*)(g_k + (bh * T_SZ + sp * KSPAN) * DH);
    const float4* vb = (const float4*)(g_v + (bh * T_SZ + sp * KSPAN) * DH);

    for (int kt = 0; kt < KSPAN; kt += TK) {
        __syncthreads();   // previous tile fully consumed
        {
            const float4* ks4 = kb + kt * 4;
            const float4* vs4 = vb + kt * 4;
            float4* sk4 = (float4*)sk;
            float4* sv4 = (float4*)sv;
#pragma unroll
            for (int i = 0; i < 4; i++) {     // 512 float4 each over 128 thr
                sk4[t + i * 128] = ks4[t + i * 128];
                sv4[t + i * 128] = vs4[t + i * 128];
            }
        }
        __syncthreads();

#pragma unroll 1
        for (int c0 = 0; c0 < TK; c0 += 16) {
            float s[16];
#pragma unroll
            for (int j = 0; j < 16; j++) {
                const ulonglong2* kr = (const ulonglong2*)(sk + (c0 + j) * DH);
                ulonglong2 kA = kr[0], kB = kr[1], kC = kr[2], kD = kr[3];
                unsigned long long a = mul2(q2[0], kA.x);
                unsigned long long c = mul2(q2[1], kA.y);
                a = fma2(q2[2], kB.x, a);
                c = fma2(q2[3], kB.y, c);
                a = fma2(q2[4], kC.x, a);
                c = fma2(q2[5], kC.y, c);
                a = fma2(q2[6], kD.x, a);
                c = fma2(q2[7], kD.y, c);
                a = add2(a, c);
                float lo, hi;
                unpack2(a, lo, hi);
                s[j] = lo + hi;                 // score in log2 units
            }

            // chunk max (tree)
            float m0 = fmaxf(s[0], s[1]),   m1 = fmaxf(s[2], s[3]);
            float m2 = fmaxf(s[4], s[5]),   m3 = fmaxf(s[6], s[7]);
            float m4 = fmaxf(s[8], s[9]),   m5 = fmaxf(s[10], s[11]);
            float m6 = fmaxf(s[12], s[13]), m7 = fmaxf(s[14], s[15]);
            m0 = fmaxf(m0, m1); m2 = fmaxf(m2, m3);
            m4 = fmaxf(m4, m5); m6 = fmaxf(m6, m7);
            m0 = fmaxf(m0, m2); m4 = fmaxf(m4, m6);
            const float mnew = fmaxf(m, fmaxf(m0, m4));

            const float corr = ex2f(m - mnew);
            const unsigned long long c2 = pack2(corr, corr);
#pragma unroll
            for (int i = 0; i < 8; i++) acc2[i] = mul2(acc2[i], c2);

            float p[16];
#pragma unroll
            for (int j = 0; j < 16; j++) p[j] = ex2f(s[j] - mnew);

            // tree-partial sum of p (breaks the 16-deep serial chain)
            float l0 = p[0] + p[1],   l1 = p[2] + p[3];
            float l2 = p[4] + p[5],   l3 = p[6] + p[7];
            float l4 = p[8] + p[9],   l5 = p[10] + p[11];
            float l6 = p[12] + p[13], l7 = p[14] + p[15];
            l0 += l1; l2 += l3; l4 += l5; l6 += l7;
            l = l * corr + ((l0 + l2) + (l4 + l6));

#pragma unroll
            for (int j = 0; j < 16; j++) {
                const unsigned long long pp = pack2(p[j], p[j]);
                const ulonglong2* vr = (const ulonglong2*)(sv + (c0 + j) * DH);
                ulonglong2 vA = vr[0], vB = vr[1], vC = vr[2], vD = vr[3];
                acc2[0] = fma2(pp, vA.x, acc2[0]);
                acc2[1] = fma2(pp, vA.y, acc2[1]);
                acc2[2] = fma2(pp, vB.x, acc2[2]);
                acc2[3] = fma2(pp, vB.y, acc2[3]);
                acc2[4] = fma2(pp, vC.x, acc2[4]);
                acc2[5] = fma2(pp, vC.y, acc2[5]);
                acc2[6] = fma2(pp, vD.x, acc2[6]);
                acc2[7] = fma2(pp, vD.y, acc2[7]);
            }
            m = mnew;
        }
    }

    // emit partials (unnormalized)
    g_pm[sp][qi] = m;
    g_pl[sp][qi] = l;
    float4* pa = (float4*)(&g_pacc[sp][qi * DH]);
#pragma unroll
    for (int i = 0; i < 4; i++) {
        float lo0, hi0, lo1, hi1;
        unpack2(acc2[2 * i], lo0, hi0);
        unpack2(acc2[2 * i + 1], lo1, hi1);
        pa[i] = make_float4(lo0, hi0, lo1, hi1);
    }
}

// ==================== Kernel 2b: split-K merge ====================
// One thread per (bh, query): combine NSPLIT partials, write normalized
// output into g_y interleaved layout [b*T + t][h*16 + d].
__global__ void __launch_bounds__(128) merge_kernel()
{
    const int qi = blockIdx.x * 128 + threadIdx.x;   // bh*T + ti
    const int bh = qi >> 12;
    const int ti = qi & 4095;

    float pm[NSPLIT];
#pragma unroll
    for (int s = 0; s < NSPLIT; s++) pm[s] = g_pm[s][qi];
    float M = fmaxf(fmaxf(pm[0], pm[1]), fmaxf(pm[2], pm[3]));

    float wgt[NSPLIT];
    float l = 0.0f;
#pragma unroll
    for (int s = 0; s < NSPLIT; s++) {
        wgt[s] = ex2f(pm[s] - M);
        l += g_pl[s][qi] * wgt[s];
    }
    const float inv = 1.0f / l;

    float acc[16];
#pragma unroll
    for (int d = 0; d < 16; d++) acc[d] = 0.0f;
#pragma unroll
    for (int s = 0; s < NSPLIT; s++) {
        const float4* pa = (const float4*)(&g_pacc[s][qi * DH]);
        const float ws = wgt[s];
#pragma unroll
        for (int i = 0; i < 4; i++) {
            float4 f = pa[i];
            acc[i * 4 + 0] += f.x * ws;
            acc[i * 4 + 1] += f.y * ws;
            acc[i * 4 + 2] += f.z * ws;
            acc[i * 4 + 3] += f.w * ws;
        }
    }

    const int h  = bh & 3;
    const int bi = bh >> 2;
    float4* yp = (float4*)(g_y + (bi * T_SZ + ti) * C_SZ + h * DH);
#pragma unroll
    for (int i = 0; i < 4; i++) {
        yp[i] = make_float4(acc[i * 4 + 0] * inv, acc[i * 4 + 1] * inv,
                            acc[i * 4 + 2] * inv, acc[i * 4 + 3] * inv);
    }
}

// ==================== Kernel 3: output projection (f32x2) ===============
__global__ void __launch_bounds__(256) proj_kernel(
    const float* __restrict__ w, const float* __restrict__ b,
    float* __restrict__ out)
{
    __shared__ float4 sw4[16 * 64];    // sw4[k4*64 + c] = w[c][4k4..]
    const int t = threadIdx.x;

    const float4* w4 = (const float4*)w;
    for (int idx = t; idx < 64 * 16; idx += 256) {
        int c = idx >> 4, k4 = idx & 15;
        sw4[k4 * 64 + c] = w4[idx];
    }
    __syncthreads();

    const int col  = t & 63;
    const int rg   = t >> 6;
    const int row0 = blockIdx.x * 64 + rg * 16;
    const float bias = b[col];

    unsigned long long acc2[16];
#pragma unroll
    for (int r = 0; r < 16; r++) acc2[r] = 0ull;

    const float4* x4 = (const float4*)g_y + row0 * 16;
#pragma unroll 4
    for (int k4 = 0; k4 < 16; k4++) {
        const float4 wv = sw4[k4 * 64 + col];
        const unsigned long long w01 = pack2(wv.x, wv.y);
        const unsigned long long w23 = pack2(wv.z, wv.w);
#pragma unroll
        for (int r = 0; r < 16; r++) {
            const float4 xv = __ldg(&x4[r * 16 + k4]);
            acc2[r] = fma2(pack2(xv.x, xv.y), w01, acc2[r]);
            acc2[r] = fma2(pack2(xv.z, xv.w), w23, acc2[r]);
        }
    }

#pragma unroll
    for (int r = 0; r < 16; r++) {
        float lo, hi;
        unpack2(acc2[r], lo, hi);
        out[(row0 + r) * 64 + col] = lo + hi + bias;
    }
}

// ==================== launch ====================
extern "C" void kernel_launch(void* const* d_in, const int* in_sizes, int n_in,
                              void* d_out, int out_size)
{
    const float* x      = (const float*)d_in[0];  // [2,4096,64]
    const float* w_attn = (const float*)d_in[1];  // [192,64]
    const float* b_attn = (const float*)d_in[2];  // [192]
    const float* w_proj = (const float*)d_in[3];  // [64,64]
    const float* b_proj = (const float*)d_in[4];  // [64]
    float* out = (float*)d_out;                   // [2,4096,64]

    qkv_kernel<<<ROWS / 16, 192>>>(x, w_attn, b_attn);

    dim3 ag(T_SZ / QB, BH, NSPLIT);   // (32, 8, 4) blocks of 128 threads
    attn_kernel<<<ag, QB>>>();

    merge_kernel<<<(BH * T_SZ) / 128, 128>>>();

    proj_kernel<<<ROWS / 64, 256>>>(w_proj, b_proj, out);
}

// round 10
// speedup vs baseline: 3.4987x; 2.3821x over previous
#include <cuda_runtime.h>
#include <cuda_bf16.h>
#include <cstdint>

// Problem constants: B=2, T=4096, C=64, H=4, Dh=16
#define B_SZ 2
#define T_SZ 4096
#define C_SZ 64
#define H_SZ 4
#define DH 16
#define BH (B_SZ * H_SZ)          // 8
#define ROWS (B_SZ * T_SZ)        // 8192

// softmax scale (1/sqrt(16)) * log2(e), folded into q before quantization
#define QSCALE 0.360673760222241f

#define TK 128                    // keys per tile
#define NT (T_SZ / TK)            // 32 tiles
#define QBLK 64                   // queries per block (4 warps x 16)

// smem row strides (bf16 units) chosen for conflict-free fragment LDS
#define KSTRIDE 20                // 16 data + 4 pad  (40B rows)
#define VSTRIDE 136               // 128 data + 8 pad (272B rows)

// -------- scratch (allocation-free rule: __device__ globals) --------
__device__ __align__(32) __nv_bfloat16 g_qh[BH * T_SZ * DH];  // q*QSCALE hi
__device__ __align__(32) __nv_bfloat16 g_ql[BH * T_SZ * DH];  // q*QSCALE lo (residual)
__device__ __align__(32) __nv_bfloat16 g_kh[BH * T_SZ * DH];  // k hi
__device__ __align__(32) __nv_bfloat16 g_kl[BH * T_SZ * DH];  // k lo
__device__ __align__(32) __nv_bfloat16 g_vt[BH * DH * T_SZ];  // v transposed [bh][d][t]
__device__ float g_y[ROWS * C_SZ];                            // attention out

// ---------------- f32x2 packed-math helpers (projections) ----------------
__device__ __forceinline__ unsigned long long pack2(float lo, float hi) {
    unsigned long long r;
    asm("mov.b64 %0, {%1, %2};" : "=l"(r) : "f"(lo), "f"(hi));
    return r;
}
__device__ __forceinline__ void unpack2(unsigned long long v, float& lo, float& hi) {
    asm("mov.b64 {%0, %1}, %2;" : "=f"(lo), "=f"(hi) : "l"(v));
}
__device__ __forceinline__ unsigned long long fma2(unsigned long long a,
                                                   unsigned long long b,
                                                   unsigned long long c) {
    unsigned long long d;
    asm("fma.rn.f32x2 %0, %1, %2, %3;" : "=l"(d) : "l"(a), "l"(b), "l"(c));
    return d;
}
__device__ __forceinline__ float ex2f(float x) {
    float y;
    asm("ex2.approx.ftz.f32 %0, %1;" : "=f"(y) : "f"(x));
    return y;
}
__device__ __forceinline__ uint32_t bf16x2_of(float lo, float hi) {
    uint32_t r;
    asm("cvt.rn.bf16x2.f32 %0, %1, %2;" : "=r"(r) : "f"(hi), "f"(lo));
    return r;
}

// mma.sync m16n8k16 row.col f32.bf16.bf16.f32, accumulating in place
__device__ __forceinline__ void mma16816(float c[4],
                                         uint32_t a0, uint32_t a1,
                                         uint32_t a2, uint32_t a3,
                                         uint32_t b0, uint32_t b1) {
    asm("mma.sync.aligned.m16n8k16.row.col.f32.bf16.bf16.f32 "
        "{%0,%1,%2,%3}, {%4,%5,%6,%7}, {%8,%9}, {%0,%1,%2,%3};"
        : "+f"(c[0]), "+f"(c[1]), "+f"(c[2]), "+f"(c[3])
        : "r"(a0), "r"(a1), "r"(a2), "r"(a3), "r"(b0), "r"(b1));
}

// ==================== Kernel 1: fused QKV projection ====================
// 192 threads, 8 rows/block. fp32 f32x2 math; emits hi/lo bf16 splits of
// (pre-scaled) Q and K, and transposed bf16 V.
__global__ void __launch_bounds__(192) qkv_kernel(
    const float* __restrict__ x, const float* __restrict__ w,
    const float* __restrict__ b)
{
    __shared__ float4 sw4[16 * 192];
    const int t = threadIdx.x;

    const float4* w4 = (const float4*)w;
    for (int idx = t; idx < 192 * 16; idx += 192) {
        int c = idx >> 4, k4 = idx & 15;
        sw4[k4 * 192 + c] = w4[idx];
    }
    __syncthreads();

    const int row0 = blockIdx.x * 8;
    const float4* x4 = (const float4*)x + row0 * 16;
    const float bias = b[t];

    unsigned long long acc2[8];
#pragma unroll
    for (int r = 0; r < 8; r++) acc2[r] = 0ull;

#pragma unroll 4
    for (int k4 = 0; k4 < 16; k4++) {
        const float4 wv = sw4[k4 * 192 + t];
        const unsigned long long w01 = pack2(wv.x, wv.y);
        const unsigned long long w23 = pack2(wv.z, wv.w);
#pragma unroll
        for (int r = 0; r < 8; r++) {
            const float4 xv = __ldg(&x4[r * 16 + k4]);
            acc2[r] = fma2(pack2(xv.x, xv.y), w01, acc2[r]);
            acc2[r] = fma2(pack2(xv.z, xv.w), w23, acc2[r]);
        }
    }

    const int which = t >> 6;          // 0=q, 1=k, 2=v
    const int cc    = t & 63;
    const int h     = cc >> 4;
    const int d     = cc & 15;

#pragma unroll
    for (int r = 0; r < 8; r++) {
        const int row = row0 + r;
        const int bi  = row >> 12;
        const int ti  = row & 4095;
        const int bh  = bi * H_SZ + h;
        float lo, hi;
        unpack2(acc2[r], lo, hi);
        float val = lo + hi + bias;
        const int qk_idx = (bh * T_SZ + ti) * DH + d;
        if (which == 0) {
            val *= QSCALE;
            __nv_bfloat16 vh = __float2bfloat16(val);
            g_qh[qk_idx] = vh;
            g_ql[qk_idx] = __float2bfloat16(val - __bfloat162float(vh));
        } else if (which == 1) {
            __nv_bfloat16 vh = __float2bfloat16(val);
            g_kh[qk_idx] = vh;
            g_kl[qk_idx] = __float2bfloat16(val - __bfloat162float(vh));
        } else {
            g_vt[(bh * DH + d) * T_SZ + ti] = __float2bfloat16(val);
        }
    }
}

// ==================== Kernel 2: mma.sync flash attention ================
// Grid (T/64, BH), 128 threads (4 warps x 16 queries). Per 128-key tile:
//   S = Qh*Kh + Qh*Kl + Ql*Kh   (3x m16n8k16 per 8-key block, fp32 acc)
//   p = exp2(S)  (no max subtraction: scores bounded, log2 domain)
//   P (bf16x2, register relayout C->A) -> Y += P*V  (m16n8k16, fp32 acc)
__global__ void __launch_bounds__(128) attn_kernel()
{
    __shared__ __nv_bfloat16 sKh[TK * KSTRIDE];   // 5 KB
    __shared__ __nv_bfloat16 sKl[TK * KSTRIDE];   // 5 KB
    __shared__ __nv_bfloat16 sVT[DH * VSTRIDE];   // 4.25 KB

    const int tid  = threadIdx.x;
    const int warp = tid >> 5;
    const int lane = tid & 31;
    const int bh   = blockIdx.y;
    const int q0w  = blockIdx.x * QBLK + warp * 16;   // this warp's 16 queries
    const int m    = lane >> 2;        // 0..7 (row group)
    const int qc   = (lane & 3) * 2;   // 0,2,4,6 (col pair)

    // ---- Q fragments (hi and lo), loaded once from global ----
    uint32_t qh0, qh1, qh2, qh3, ql0, ql1, ql2, ql3;
    {
        const size_t r0 = ((size_t)(bh * T_SZ + q0w + m)) * DH + qc;
        const size_t r1 = r0 + 8 * DH;
        qh0 = *(const uint32_t*)(g_qh + r0);
        qh1 = *(const uint32_t*)(g_qh + r1);
        qh2 = *(const uint32_t*)(g_qh + r0 + 8);
        qh3 = *(const uint32_t*)(g_qh + r1 + 8);
        ql0 = *(const uint32_t*)(g_ql + r0);
        ql1 = *(const uint32_t*)(g_ql + r1);
        ql2 = *(const uint32_t*)(g_ql + r0 + 8);
        ql3 = *(const uint32_t*)(g_ql + r1 + 8);
    }

    float Y0[4] = {0.f, 0.f, 0.f, 0.f};   // out cols qc..qc+1 (d 0-7 half)
    float Y1[4] = {0.f, 0.f, 0.f, 0.f};   // out cols qc+8..   (d 8-15 half)
    float l0 = 0.f, l1 = 0.f;             // row sums (rows m, m+8)

    const __nv_bfloat16* khb = g_kh + (size_t)bh * T_SZ * DH;
    const __nv_bfloat16* klb = g_kl + (size_t)bh * T_SZ * DH;
    const __nv_bfloat16* vtb = g_vt + (size_t)bh * DH * T_SZ;

    // coop-load thread mapping (128 threads)
    const int vrow = tid >> 3, vchunk = tid & 7;      // V: 16 rows x 8 chunks

    for (int nt = 0; nt < NT; nt++) {
        const int kt = nt * TK;
        __syncthreads();
        // ---- cooperative tile load ----
        {
            // K: thread = key row (32B hi + 32B lo)
            const uint2* sh = (const uint2*)(khb + (size_t)(kt + tid) * DH);
            const uint2* sl = (const uint2*)(klb + (size_t)(kt + tid) * DH);
            uint2* dh = (uint2*)(sKh + tid * KSTRIDE);
            uint2* dl = (uint2*)(sKl + tid * KSTRIDE);
#pragma unroll
            for (int i = 0; i < 4; i++) { dh[i] = sh[i]; dl[i] = sl[i]; }
            // V^T: 16 d-rows x 8 chunks of 16 keys
            const uint4* vs = (const uint4*)(vtb + (size_t)vrow * T_SZ + kt + vchunk * 16);
            uint4* vd = (uint4*)(sVT + vrow * VSTRIDE + vchunk * 16);
            vd[0] = vs[0];
            vd[1] = vs[1];
        }
        __syncthreads();

#pragma unroll 2
        for (int st = 0; st < 8; st++) {
            const int key0 = st * 16;
            float s0[4] = {0.f, 0.f, 0.f, 0.f};
            float s1[4] = {0.f, 0.f, 0.f, 0.f};
            // ---- S for keys [key0, key0+8) ----
            {
                const __nv_bfloat16* kp = sKh + (key0 + m) * KSTRIDE + qc;
                const __nv_bfloat16* lp = sKl + (key0 + m) * KSTRIDE + qc;
                uint32_t bh0 = *(const uint32_t*)kp;
                uint32_t bh1 = *(const uint32_t*)(kp + 8);
                uint32_t bl0 = *(const uint32_t*)lp;
                uint32_t bl1 = *(const uint32_t*)(lp + 8);
                mma16816(s0, qh0, qh1, qh2, qh3, bh0, bh1);
                mma16816(s0, qh0, qh1, qh2, qh3, bl0, bl1);
                mma16816(s0, ql0, ql1, ql2, ql3, bh0, bh1);
            }
            // ---- S for keys [key0+8, key0+16) ----
            {
                const __nv_bfloat16* kp = sKh + (key0 + 8 + m) * KSTRIDE + qc;
                const __nv_bfloat16* lp = sKl + (key0 + 8 + m) * KSTRIDE + qc;
                uint32_t bh0 = *(const uint32_t*)kp;
                uint32_t bh1 = *(const uint32_t*)(kp + 8);
                uint32_t bl0 = *(const uint32_t*)lp;
                uint32_t bl1 = *(const uint32_t*)(lp + 8);
                mma16816(s1, qh0, qh1, qh2, qh3, bh0, bh1);
                mma16816(s1, qh0, qh1, qh2, qh3, bl0, bl1);
                mma16816(s1, ql0, ql1, ql2, ql3, bh0, bh1);
            }
            // ---- softmax numerator (log2 domain, no max-sub) ----
            float p00 = ex2f(s0[0]), p01 = ex2f(s0[1]);
            float p02 = ex2f(s0[2]), p03 = ex2f(s0[3]);
            float p10 = ex2f(s1[0]), p11 = ex2f(s1[1]);
            float p12 = ex2f(s1[2]), p13 = ex2f(s1[3]);
            l0 += (p00 + p01) + (p10 + p11);
            l1 += (p02 + p03) + (p12 + p13);
            // C-fragment -> A-fragment (pure register relayout)
            uint32_t a0 = bf16x2_of(p00, p01);
            uint32_t a1 = bf16x2_of(p02, p03);
            uint32_t a2 = bf16x2_of(p10, p11);
            uint32_t a3 = bf16x2_of(p12, p13);
            // ---- Y += P * V ----
            const __nv_bfloat16* vp = sVT + m * VSTRIDE + key0 + qc;
            uint32_t vb0 = *(const uint32_t*)vp;
            uint32_t vb1 = *(const uint32_t*)(vp + 8);
            mma16816(Y0, a0, a1, a2, a3, vb0, vb1);
            uint32_t vc0 = *(const uint32_t*)(vp + 8 * VSTRIDE);
            uint32_t vc1 = *(const uint32_t*)(vp + 8 * VSTRIDE + 8);
            mma16816(Y1, a0, a1, a2, a3, vc0, vc1);
        }
    }

    // ---- reduce l across the 4 threads of each row quad ----
    l0 += __shfl_xor_sync(0xffffffffu, l0, 1);
    l0 += __shfl_xor_sync(0xffffffffu, l0, 2);
    l1 += __shfl_xor_sync(0xffffffffu, l1, 1);
    l1 += __shfl_xor_sync(0xffffffffu, l1, 2);
    const float inv0 = 1.0f / l0;
    const float inv1 = 1.0f / l1;

    // ---- write normalized output ----
    const int h  = bh & 3;
    const int bi = bh >> 2;
    const int colb = h * DH + qc;
    float* y0 = g_y + ((size_t)(bi * T_SZ + q0w + m)) * C_SZ + colb;
    float* y1 = g_y + ((size_t)(bi * T_SZ + q0w + m + 8)) * C_SZ + colb;
    *(float2*)(y0)     = make_float2(Y0[0] * inv0, Y0[1] * inv0);
    *(float2*)(y0 + 8) = make_float2(Y1[0] * inv0, Y1[1] * inv0);
    *(float2*)(y1)     = make_float2(Y0[2] * inv1, Y0[3] * inv1);
    *(float2*)(y1 + 8) = make_float2(Y1[2] * inv1, Y1[3] * inv1);
}

// ==================== Kernel 3: output projection (f32x2) ===============
__global__ void __launch_bounds__(256) proj_kernel(
    const float* __restrict__ w, const float* __restrict__ b,
    float* __restrict__ out)
{
    __shared__ float4 sw4[16 * 64];
    const int t = threadIdx.x;

    const float4* w4 = (const float4*)w;
    for (int idx = t; idx < 64 * 16; idx += 256) {
        int c = idx >> 4, k4 = idx & 15;
        sw4[k4 * 64 + c] = w4[idx];
    }
    __syncthreads();

    const int col  = t & 63;
    const int rg   = t >> 6;
    const int row0 = blockIdx.x * 32 + rg * 8;
    const float bias = b[col];

    unsigned long long acc2[8];
#pragma unroll
    for (int r = 0; r < 8; r++) acc2[r] = 0ull;

    const float4* x4 = (const float4*)g_y + row0 * 16;
#pragma unroll 4
    for (int k4 = 0; k4 < 16; k4++) {
        const float4 wv = sw4[k4 * 64 + col];
        const unsigned long long w01 = pack2(wv.x, wv.y);
        const unsigned long long w23 = pack2(wv.z, wv.w);
#pragma unroll
        for (int r = 0; r < 8; r++) {
            const float4 xv = __ldg(&x4[r * 16 + k4]);
            acc2[r] = fma2(pack2(xv.x, xv.y), w01, acc2[r]);
            acc2[r] = fma2(pack2(xv.z, xv.w), w23, acc2[r]);
        }
    }

#pragma unroll
    for (int r = 0; r < 8; r++) {
        float lo, hi;
        unpack2(acc2[r], lo, hi);
        out[(row0 + r) * 64 + col] = lo + hi + bias;
    }
}

// ==================== launch ====================
extern "C" void kernel_launch(void* const* d_in, const int* in_sizes, int n_in,
                              void* d_out, int out_size)
{
    const float* x      = (const float*)d_in[0];  // [2,4096,64]
    const float* w_attn = (const float*)d_in[1];  // [192,64]
    const float* b_attn = (const float*)d_in[2];  // [192]
    const float* w_proj = (const float*)d_in[3];  // [64,64]
    const float* b_proj = (const float*)d_in[4];  // [64]
    float* out = (float*)d_out;                   // [2,4096,64]

    qkv_kernel<<<ROWS / 8, 192>>>(x, w_attn, b_attn);

    dim3 ag(T_SZ / QBLK, BH);   // (64, 8) = 512 blocks of 128 threads
    attn_kernel<<<ag, 128>>>();

    proj_kernel<<<ROWS / 32, 256>>>(w_proj, b_proj, out);
}

// round 11
// speedup vs baseline: 4.3184x; 1.2343x over previous
#include <cuda_runtime.h>
#include <cuda_bf16.h>
#include <cstdint>

// Problem constants: B=2, T=4096, C=64, H=4, Dh=16
#define B_SZ 2
#define T_SZ 4096
#define C_SZ 64
#define H_SZ 4
#define DH 16
#define BH (B_SZ * H_SZ)          // 8
#define ROWS (B_SZ * T_SZ)        // 8192

// softmax scale (1/sqrt(16)) * log2(e), folded into q before quantization
#define QSCALE 0.360673760222241f

#define TK 128                    // keys per tile
#define NT (T_SZ / TK)            // 32 tiles
#define QBLK 128                  // queries per block (4 warps x 32)

// smem row strides (bf16 units), conflict-free fragment LDS
#define KSTRIDE 24                // 16 data + 8 pad (48B rows; 12 words -> 12m+b distinct mod 32)
#define VSTRIDE 136               // 128 data + 8 pad (272B rows; 68 mod 32 = 4 -> 4m+b distinct)

// -------- scratch (allocation-free rule: __device__ globals) --------
__device__ __align__(32) __nv_bfloat16 g_qh[BH * T_SZ * DH];  // q*QSCALE hi
__device__ __align__(32) __nv_bfloat16 g_ql[BH * T_SZ * DH];  // q*QSCALE lo (residual)
__device__ __align__(32) __nv_bfloat16 g_kh[BH * T_SZ * DH];  // k (bf16)
__device__ __align__(32) __nv_bfloat16 g_vt[BH * DH * T_SZ];  // v transposed [bh][d][t]
__device__ float g_y[ROWS * C_SZ];                            // attention out

// ---------------- f32x2 packed-math helpers (projections) ----------------
__device__ __forceinline__ unsigned long long pack2(float lo, float hi) {
    unsigned long long r;
    asm("mov.b64 %0, {%1, %2};" : "=l"(r) : "f"(lo), "f"(hi));
    return r;
}
__device__ __forceinline__ void unpack2(unsigned long long v, float& lo, float& hi) {
    asm("mov.b64 {%0, %1}, %2;" : "=f"(lo), "=f"(hi) : "l"(v));
}
__device__ __forceinline__ unsigned long long fma2(unsigned long long a,
                                                   unsigned long long b,
                                                   unsigned long long c) {
    unsigned long long d;
    asm("fma.rn.f32x2 %0, %1, %2, %3;" : "=l"(d) : "l"(a), "l"(b), "l"(c));
    return d;
}
__device__ __forceinline__ float ex2f(float x) {
    float y;
    asm("ex2.approx.ftz.f32 %0, %1;" : "=f"(y) : "f"(x));
    return y;
}
__device__ __forceinline__ uint32_t bf16x2_of(float lo, float hi) {
    uint32_t r;
    asm("cvt.rn.bf16x2.f32 %0, %1, %2;" : "=r"(r) : "f"(hi), "f"(lo));
    return r;
}

// mma.sync m16n8k16 row.col f32.bf16.bf16.f32, accumulating in place
__device__ __forceinline__ void mma16816(float c[4],
                                         uint32_t a0, uint32_t a1,
                                         uint32_t a2, uint32_t a3,
                                         uint32_t b0, uint32_t b1) {
    asm("mma.sync.aligned.m16n8k16.row.col.f32.bf16.bf16.f32 "
        "{%0,%1,%2,%3}, {%4,%5,%6,%7}, {%8,%9}, {%0,%1,%2,%3};"
        : "+f"(c[0]), "+f"(c[1]), "+f"(c[2]), "+f"(c[3])
        : "r"(a0), "r"(a1), "r"(a2), "r"(a3), "r"(b0), "r"(b1));
}

// ==================== Kernel 1: fused QKV projection ====================
// 192 threads, 16 rows/block. x tile staged through smem (no redundant LDG
// broadcasts). Emits bf16 Qh/Ql (pre-scaled), bf16 K, transposed bf16 V.
__global__ void __launch_bounds__(192) qkv_kernel(
    const float* __restrict__ x, const float* __restrict__ w,
    const float* __restrict__ b)
{
    __shared__ float4 sw4[16 * 192];   // [k4][c]  48KB
    __shared__ float4 sx4[16 * 16];    // [r][k4]  4KB
    const int t = threadIdx.x;

    const float4* w4 = (const float4*)w;          // w4[c*16 + k4]
    for (int idx = t; idx < 192 * 16; idx += 192) {
        int c = idx >> 4, k4 = idx & 15;
        sw4[k4 * 192 + c] = w4[idx];
    }
    const float4* x4 = (const float4*)x + blockIdx.x * 256;   // 16 rows x 16 f4
    for (int idx = t; idx < 256; idx += 192) sx4[idx] = x4[idx];
    __syncthreads();

    const int row0 = blockIdx.x * 16;
    const float bias = b[t];

    unsigned long long acc2[16];
#pragma unroll
    for (int r = 0; r < 16; r++) acc2[r] = 0ull;

#pragma unroll 4
    for (int k4 = 0; k4 < 16; k4++) {
        const float4 wv = sw4[k4 * 192 + t];
        const unsigned long long w01 = pack2(wv.x, wv.y);
        const unsigned long long w23 = pack2(wv.z, wv.w);
#pragma unroll
        for (int r = 0; r < 16; r++) {
            const float4 xv = sx4[r * 16 + k4];   // LDS broadcast
            acc2[r] = fma2(pack2(xv.x, xv.y), w01, acc2[r]);
            acc2[r] = fma2(pack2(xv.z, xv.w), w23, acc2[r]);
        }
    }

    const int which = t >> 6;          // 0=q, 1=k, 2=v
    const int cc    = t & 63;
    const int h     = cc >> 4;
    const int d     = cc & 15;

#pragma unroll
    for (int r = 0; r < 16; r++) {
        const int row = row0 + r;
        const int bi  = row >> 12;
        const int ti  = row & 4095;
        const int bh  = bi * H_SZ + h;
        float lo, hi;
        unpack2(acc2[r], lo, hi);
        float val = lo + hi + bias;
        const int qk_idx = (bh * T_SZ + ti) * DH + d;
        if (which == 0) {
            val *= QSCALE;
            __nv_bfloat16 vh = __float2bfloat16(val);
            g_qh[qk_idx] = vh;
            g_ql[qk_idx] = __float2bfloat16(val - __bfloat162float(vh));
        } else if (which == 1) {
            g_kh[qk_idx] = __float2bfloat16(val);
        } else {
            g_vt[(bh * DH + d) * T_SZ + ti] = __float2bfloat16(val);
        }
    }
}

// ==================== Kernel 2: mma.sync flash attention ================
// Grid (T/128, BH), 128 threads (4 warps x 32 queries, 2 m16 groups each).
// S = (Qh+Ql)*K (2 mmas per 8-key group; q-quant fully compensated),
// p = exp2(S) (log2 domain, no max-sub: scores bounded), Y += P*V.
__global__ void __launch_bounds__(128) attn_kernel()
{
    __shared__ __nv_bfloat16 sKh[TK * KSTRIDE];   // 6 KB
    __shared__ __nv_bfloat16 sVT[DH * VSTRIDE];   // 4.25 KB

    const int tid  = threadIdx.x;
    const int warp = tid >> 5;
    const int lane = tid & 31;
    const int bh   = blockIdx.y;
    const int q0w  = blockIdx.x * QBLK + warp * 32;   // this warp's 32 queries
    const int m    = lane >> 2;        // 0..7 (row group)
    const int qc   = (lane & 3) * 2;   // 0,2,4,6 (col pair)

    // ---- Q fragments for 2 query groups (hi and lo), loaded once ----
    uint32_t qh[2][4], ql[2][4];
#pragma unroll
    for (int g = 0; g < 2; g++) {
        const size_t r0 = ((size_t)(bh * T_SZ + q0w + g * 16 + m)) * DH + qc;
        const size_t r1 = r0 + 8 * DH;
        qh[g][0] = *(const uint32_t*)(g_qh + r0);
        qh[g][1] = *(const uint32_t*)(g_qh + r1);
        qh[g][2] = *(const uint32_t*)(g_qh + r0 + 8);
        qh[g][3] = *(const uint32_t*)(g_qh + r1 + 8);
        ql[g][0] = *(const uint32_t*)(g_ql + r0);
        ql[g][1] = *(const uint32_t*)(g_ql + r1);
        ql[g][2] = *(const uint32_t*)(g_ql + r0 + 8);
        ql[g][3] = *(const uint32_t*)(g_ql + r1 + 8);
    }

    float Y[2][2][4];           // [qgroup][d-half][frag]
#pragma unroll
    for (int g = 0; g < 2; g++)
#pragma unroll
        for (int hh = 0; hh < 2; hh++)
#pragma unroll
            for (int i = 0; i < 4; i++) Y[g][hh][i] = 0.f;
    float lsum[2][2] = {{0.f, 0.f}, {0.f, 0.f}};   // [qgroup][row-half]

    const __nv_bfloat16* khb = g_kh + (size_t)bh * T_SZ * DH;
    const __nv_bfloat16* vtb = g_vt + (size_t)bh * DH * T_SZ;

    const int vrow = tid >> 3, vchunk = tid & 7;   // V coop: 16 rows x 8 chunks

    for (int nt = 0; nt < NT; nt++) {
        const int kt = nt * TK;
        __syncthreads();
        // ---- cooperative tile load ----
        {
            // K: thread = key row (32B), 48B-stride rows (16B pad)
            const uint4* sh = (const uint4*)(khb + (size_t)(kt + tid) * DH);
            uint4* dh = (uint4*)(sKh + tid * KSTRIDE);
            dh[0] = sh[0];
            dh[1] = sh[1];
            // V^T: 16 d-rows x 8 chunks of 16 keys
            const uint4* vs = (const uint4*)(vtb + (size_t)vrow * T_SZ + kt + vchunk * 16);
            uint4* vd = (uint4*)(sVT + vrow * VSTRIDE + vchunk * 16);
            vd[0] = vs[0];
            vd[1] = vs[1];
        }
        __syncthreads();

#pragma unroll 2
        for (int st = 0; st < 8; st++) {
            const int key0 = st * 16;
            // K fragments (shared across both query groups)
            const __nv_bfloat16* kp0 = sKh + (key0 + m) * KSTRIDE + qc;
            const __nv_bfloat16* kp1 = kp0 + 8 * KSTRIDE;
            const uint32_t b00 = *(const uint32_t*)kp0;
            const uint32_t b01 = *(const uint32_t*)(kp0 + 8);
            const uint32_t b10 = *(const uint32_t*)kp1;
            const uint32_t b11 = *(const uint32_t*)(kp1 + 8);
            // V fragments (shared across both query groups)
            const __nv_bfloat16* vp = sVT + m * VSTRIDE + key0 + qc;
            const uint32_t vb0 = *(const uint32_t*)vp;
            const uint32_t vb1 = *(const uint32_t*)(vp + 8);
            const uint32_t vc0 = *(const uint32_t*)(vp + 8 * VSTRIDE);
            const uint32_t vc1 = *(const uint32_t*)(vp + 8 * VSTRIDE + 8);

#pragma unroll
            for (int g = 0; g < 2; g++) {
                float s0[4] = {0.f, 0.f, 0.f, 0.f};
                float s1[4] = {0.f, 0.f, 0.f, 0.f};
                mma16816(s0, qh[g][0], qh[g][1], qh[g][2], qh[g][3], b00, b01);
                mma16816(s0, ql[g][0], ql[g][1], ql[g][2], ql[g][3], b00, b01);
                mma16816(s1, qh[g][0], qh[g][1], qh[g][2], qh[g][3], b10, b11);
                mma16816(s1, ql[g][0], ql[g][1], ql[g][2], ql[g][3], b10, b11);

                const float p00 = ex2f(s0[0]), p01 = ex2f(s0[1]);
                const float p02 = ex2f(s0[2]), p03 = ex2f(s0[3]);
                const float p10 = ex2f(s1[0]), p11 = ex2f(s1[1]);
                const float p12 = ex2f(s1[2]), p13 = ex2f(s1[3]);
                lsum[g][0] += (p00 + p01) + (p10 + p11);
                lsum[g][1] += (p02 + p03) + (p12 + p13);

                const uint32_t a0 = bf16x2_of(p00, p01);
                const uint32_t a1 = bf16x2_of(p02, p03);
                const uint32_t a2 = bf16x2_of(p10, p11);
                const uint32_t a3 = bf16x2_of(p12, p13);
                mma16816(Y[g][0], a0, a1, a2, a3, vb0, vb1);
                mma16816(Y[g][1], a0, a1, a2, a3, vc0, vc1);
            }
        }
    }

    // ---- reduce l across the 4 threads of each row quad; write out ----
    const int h  = bh & 3;
    const int bi = bh >> 2;
    const int colb = h * DH + qc;
#pragma unroll
    for (int g = 0; g < 2; g++) {
        float l0 = lsum[g][0], l1 = lsum[g][1];
        l0 += __shfl_xor_sync(0xffffffffu, l0, 1);
        l0 += __shfl_xor_sync(0xffffffffu, l0, 2);
        l1 += __shfl_xor_sync(0xffffffffu, l1, 1);
        l1 += __shfl_xor_sync(0xffffffffu, l1, 2);
        const float inv0 = 1.0f / l0;
        const float inv1 = 1.0f / l1;
        float* y0 = g_y + ((size_t)(bi * T_SZ + q0w + g * 16 + m)) * C_SZ + colb;
        float* y1 = y0 + 8 * C_SZ;
        *(float2*)(y0)     = make_float2(Y[g][0][0] * inv0, Y[g][0][1] * inv0);
        *(float2*)(y0 + 8) = make_float2(Y[g][1][0] * inv0, Y[g][1][1] * inv0);
        *(float2*)(y1)     = make_float2(Y[g][0][2] * inv1, Y[g][0][3] * inv1);
        *(float2*)(y1 + 8) = make_float2(Y[g][1][2] * inv1, Y[g][1][3] * inv1);
    }
}

// ==================== Kernel 3: output projection (f32x2) ===============
// 256 threads, 32 rows/block; y tile staged through smem.
__global__ void __launch_bounds__(256) proj_kernel(
    const float* __restrict__ w, const float* __restrict__ b,
    float* __restrict__ out)
{
    __shared__ float4 sw4[16 * 64];    // 16KB
    __shared__ float4 sx4[32 * 16];    // 8KB: [r][k4]
    const int t = threadIdx.x;

    const float4* w4 = (const float4*)w;
    for (int idx = t; idx < 64 * 16; idx += 256) {
        int c = idx >> 4, k4 = idx & 15;
        sw4[k4 * 64 + c] = w4[idx];
    }
    const float4* x4 = (const float4*)g_y + blockIdx.x * 512;   // 32 rows x 16 f4
    for (int idx = t; idx < 512; idx += 256) sx4[idx] = x4[idx];
    __syncthreads();

    const int col  = t & 63;
    const int rg   = t >> 6;
    const int row0 = blockIdx.x * 32 + rg * 8;
    const float bias = b[col];

    unsigned long long acc2[8];
#pragma unroll
    for (int r = 0; r < 8; r++) acc2[r] = 0ull;

#pragma unroll 4
    for (int k4 = 0; k4 < 16; k4++) {
        const float4 wv = sw4[k4 * 64 + col];
        const unsigned long long w01 = pack2(wv.x, wv.y);
        const unsigned long long w23 = pack2(wv.z, wv.w);
#pragma unroll
        for (int r = 0; r < 8; r++) {
            const float4 xv = sx4[(rg * 8 + r) * 16 + k4];   // LDS broadcast
            acc2[r] = fma2(pack2(xv.x, xv.y), w01, acc2[r]);
            acc2[r] = fma2(pack2(xv.z, xv.w), w23, acc2[r]);
        }
    }

#pragma unroll
    for (int r = 0; r < 8; r++) {
        float lo, hi;
        unpack2(acc2[r], lo, hi);
        out[(row0 + r) * 64 + col] = lo + hi + bias;
    }
}

// ==================== launch ====================
extern "C" void kernel_launch(void* const* d_in, const int* in_sizes, int n_in,
                              void* d_out, int out_size)
{
    const float* x      = (const float*)d_in[0];  // [2,4096,64]
    const float* w_attn = (const float*)d_in[1];  // [192,64]
    const float* b_attn = (const float*)d_in[2];  // [192]
    const float* w_proj = (const float*)d_in[3];  // [64,64]
    const float* b_proj = (const float*)d_in[4];  // [64]
    float* out = (float*)d_out;                   // [2,4096,64]

    qkv_kernel<<<ROWS / 16, 192>>>(x, w_attn, b_attn);

    dim3 ag(T_SZ / QBLK, BH);   // (32, 8) blocks of 128 threads
    attn_kernel<<<ag, 128>>>();

    proj_kernel<<<ROWS / 32, 256>>>(w_proj, b_proj, out);
}

// round 12
// speedup vs baseline: 5.0073x; 1.1595x over previous
#include <cuda_runtime.h>
#include <cuda_bf16.h>
#include <cuda_fp16.h>
#include <cstdint>

// Problem constants: B=2, T=4096, C=64, H=4, Dh=16
#define B_SZ 2
#define T_SZ 4096
#define C_SZ 64
#define H_SZ 4
#define DH 16
#define BH (B_SZ * H_SZ)          // 8
#define ROWS (B_SZ * T_SZ)        // 8192

// softmax scale (1/sqrt(16)) * log2(e), folded into q before quantization
#define QSCALE 0.360673760222241f

#define TK 128                    // keys per tile
#define NT (T_SZ / TK)            // 32 tiles
#define QBLK 128                  // queries per block (4 warps x 32)

// smem row strides (fp16 units), conflict-free fragment LDS
#define KSTRIDE 24                // 16 data + 8 pad (48B rows)
#define VSTRIDE 136               // 128 data + 8 pad (272B rows)

// -------- scratch (allocation-free rule: __device__ globals) --------
__device__ __align__(32) __half g_qh[BH * T_SZ * DH];  // q*QSCALE (fp16)
__device__ __align__(32) __half g_kh[BH * T_SZ * DH];  // k (fp16)
__device__ __align__(32) __half g_vt[BH * DH * T_SZ];  // v transposed [bh][d][t]
__device__ float g_y[ROWS * C_SZ];                     // attention out

// ---------------- f32x2 packed-math helpers (projections) ----------------
__device__ __forceinline__ unsigned long long pack2(float lo, float hi) {
    unsigned long long r;
    asm("mov.b64 %0, {%1, %2};" : "=l"(r) : "f"(lo), "f"(hi));
    return r;
}
__device__ __forceinline__ void unpack2(unsigned long long v, float& lo, float& hi) {
    asm("mov.b64 {%0, %1}, %2;" : "=f"(lo), "=f"(hi) : "l"(v));
}
__device__ __forceinline__ unsigned long long fma2(unsigned long long a,
                                                   unsigned long long b,
                                                   unsigned long long c) {
    unsigned long long d;
    asm("fma.rn.f32x2 %0, %1, %2, %3;" : "=l"(d) : "l"(a), "l"(b), "l"(c));
    return d;
}

// ---------------- fp16 attention helpers ----------------
// pack 2 fp32 -> f16x2 (first operand = high half, matching cvt convention)
__device__ __forceinline__ uint32_t f16x2_of(float lo, float hi) {
    uint32_t r;
    asm("cvt.rn.f16x2.f32 %0, %1, %2;" : "=r"(r) : "f"(hi), "f"(lo));
    return r;
}
// dual exp2 on packed halves (one MUFU op for two exps)
__device__ __forceinline__ uint32_t ex2h2(uint32_t s) {
    uint32_t d;
    asm("ex2.approx.f16x2 %0, %1;" : "=r"(d) : "r"(s));
    return d;
}

// mma.sync m16n8k16 row.col f32.f16.f16.f32, accumulating in place
__device__ __forceinline__ void mma16816h(float c[4],
                                          uint32_t a0, uint32_t a1,
                                          uint32_t a2, uint32_t a3,
                                          uint32_t b0, uint32_t b1) {
    asm("mma.sync.aligned.m16n8k16.row.col.f32.f16.f16.f32 "
        "{%0,%1,%2,%3}, {%4,%5,%6,%7}, {%8,%9}, {%0,%1,%2,%3};"
        : "+f"(c[0]), "+f"(c[1]), "+f"(c[2]), "+f"(c[3])
        : "r"(a0), "r"(a1), "r"(a2), "r"(a3), "r"(b0), "r"(b1));
}

// ==================== Kernel 1: fused QKV projection ====================
// Grid (ROWS/16, 2): each block does 16 rows x 96 cols (half the outputs).
// 192 threads = 96 cols x 2 row-groups of 8. 24KB weight + 4KB x smem.
__global__ void __launch_bounds__(192) qkv_kernel(
    const float* __restrict__ x, const float* __restrict__ w,
    const float* __restrict__ b)
{
    __shared__ float4 sw4[16 * 96];    // [k4][c96]  24KB
    __shared__ float4 sx4[16 * 16];    // [r][k4]    4KB
    const int t = threadIdx.x;
    const int chalf = blockIdx.y;

    const float4* w4 = (const float4*)w;          // w4[c*16 + k4]
    for (int idx = t; idx < 96 * 16; idx += 192) {
        int c = idx >> 4, k4 = idx & 15;
        sw4[k4 * 96 + c] = w4[(chalf * 96 + c) * 16 + k4];
    }
    const float4* x4 = (const float4*)x + blockIdx.x * 256;   // 16 rows x 16 f4
    for (int idx = t; idx < 256; idx += 192) sx4[idx] = x4[idx];
    __syncthreads();

    const int cl  = t % 96;            // local col
    const int rg  = t / 96;            // row group 0/1
    const int col = chalf * 96 + cl;   // global col 0..191
    const int row0 = blockIdx.x * 16 + rg * 8;
    const float bias = b[col];

    unsigned long long acc2[8];
#pragma unroll
    for (int r = 0; r < 8; r++) acc2[r] = 0ull;

#pragma unroll 4
    for (int k4 = 0; k4 < 16; k4++) {
        const float4 wv = sw4[k4 * 96 + cl];
        const unsigned long long w01 = pack2(wv.x, wv.y);
        const unsigned long long w23 = pack2(wv.z, wv.w);
#pragma unroll
        for (int r = 0; r < 8; r++) {
            const float4 xv = sx4[(rg * 8 + r) * 16 + k4];   // LDS broadcast
            acc2[r] = fma2(pack2(xv.x, xv.y), w01, acc2[r]);
            acc2[r] = fma2(pack2(xv.z, xv.w), w23, acc2[r]);
        }
    }

    const int which = col >> 6;        // 0=q, 1=k, 2=v
    const int cc    = col & 63;
    const int h     = cc >> 4;
    const int d     = cc & 15;

#pragma unroll
    for (int r = 0; r < 8; r++) {
        const int row = row0 + r;
        const int bi  = row >> 12;
        const int ti  = row & 4095;
        const int bh  = bi * H_SZ + h;
        float lo, hi;
        unpack2(acc2[r], lo, hi);
        const float val = lo + hi + bias;
        if (which == 0)
            g_qh[(bh * T_SZ + ti) * DH + d] = __float2half(val * QSCALE);
        else if (which == 1)
            g_kh[(bh * T_SZ + ti) * DH + d] = __float2half(val);
        else
            g_vt[(bh * DH + d) * T_SZ + ti] = __float2half(val);
    }
}

// ==================== Kernel 2: fp16 mma.sync flash attention ===========
// Grid (T/128, BH), 128 threads (4 warps x 32 queries, 2 m16 groups each).
// S = Q*K (fp16 in, fp32 acc), p = ex2.f16x2(S) -> PV A-fragment directly.
// Row sums via ones-column mma (fp32, tensor pipe). No max subtraction
// (log2-domain scores are bounded; QSCALE folded into q).
__global__ void __launch_bounds__(128) attn_kernel()
{
    __shared__ __half sKh[TK * KSTRIDE];   // 6 KB
    __shared__ __half sVT[DH * VSTRIDE];   // 4.25 KB

    const int tid  = threadIdx.x;
    const int warp = tid >> 5;
    const int lane = tid & 31;
    const int bh   = blockIdx.y;
    const int q0w  = blockIdx.x * QBLK + warp * 32;   // this warp's 32 queries
    const int m    = lane >> 2;        // 0..7 (row group)
    const int qc   = (lane & 3) * 2;   // 0,2,4,6 (col pair)

    // ones-column B fragment (col 0 = 1.0 for all 16 k): lanes 0-3 hold k rows
    const uint32_t ones = (lane < 4) ? 0x3C003C00u : 0u;

    // ---- Q fragments for 2 query groups, loaded once ----
    uint32_t qf[2][4];
#pragma unroll
    for (int g = 0; g < 2; g++) {
        const size_t r0 = ((size_t)(bh * T_SZ + q0w + g * 16 + m)) * DH + qc;
        const size_t r1 = r0 + 8 * DH;
        qf[g][0] = *(const uint32_t*)(g_qh + r0);
        qf[g][1] = *(const uint32_t*)(g_qh + r1);
        qf[g][2] = *(const uint32_t*)(g_qh + r0 + 8);
        qf[g][3] = *(const uint32_t*)(g_qh + r1 + 8);
    }

    float Y[2][2][4];           // [qgroup][d-half][frag]
    float L[2][4];              // [qgroup][frag] — ones-mma row sums
#pragma unroll
    for (int g = 0; g < 2; g++) {
#pragma unroll
        for (int i = 0; i < 4; i++) { Y[g][0][i] = 0.f; Y[g][1][i] = 0.f; L[g][i] = 0.f; }
    }

    const __half* khb = g_kh + (size_t)bh * T_SZ * DH;
    const __half* vtb = g_vt + (size_t)bh * DH * T_SZ;

    const int vrow = tid >> 3, vchunk = tid & 7;   // V coop: 16 rows x 8 chunks

    for (int nt = 0; nt < NT; nt++) {
        const int kt = nt * TK;
        __syncthreads();
        // ---- cooperative tile load ----
        {
            // K: thread = key row (32B), 48B-stride rows
            const uint4* sh = (const uint4*)(khb + (size_t)(kt + tid) * DH);
            uint4* dh = (uint4*)(sKh + tid * KSTRIDE);
            dh[0] = sh[0];
            dh[1] = sh[1];
            // V^T: 16 d-rows x 8 chunks of 16 keys
            const uint4* vs = (const uint4*)(vtb + (size_t)vrow * T_SZ + kt + vchunk * 16);
            uint4* vd = (uint4*)(sVT + vrow * VSTRIDE + vchunk * 16);
            vd[0] = vs[0];
            vd[1] = vs[1];
        }
        __syncthreads();

#pragma unroll 2
        for (int st = 0; st < 8; st++) {
            const int key0 = st * 16;
            // K fragments (shared across both query groups)
            const __half* kp0 = sKh + (key0 + m) * KSTRIDE + qc;
            const __half* kp1 = kp0 + 8 * KSTRIDE;
            const uint32_t b00 = *(const uint32_t*)kp0;
            const uint32_t b01 = *(const uint32_t*)(kp0 + 8);
            const uint32_t b10 = *(const uint32_t*)kp1;
            const uint32_t b11 = *(const uint32_t*)(kp1 + 8);
            // V fragments (shared across both query groups)
            const __half* vp = sVT + m * VSTRIDE + key0 + qc;
            const uint32_t vb0 = *(const uint32_t*)vp;
            const uint32_t vb1 = *(const uint32_t*)(vp + 8);
            const uint32_t vc0 = *(const uint32_t*)(vp + 8 * VSTRIDE);
            const uint32_t vc1 = *(const uint32_t*)(vp + 8 * VSTRIDE + 8);

#pragma unroll
            for (int g = 0; g < 2; g++) {
                float s0[4] = {0.f, 0.f, 0.f, 0.f};
                float s1[4] = {0.f, 0.f, 0.f, 0.f};
                mma16816h(s0, qf[g][0], qf[g][1], qf[g][2], qf[g][3], b00, b01);
                mma16816h(s1, qf[g][0], qf[g][1], qf[g][2], qf[g][3], b10, b11);

                // p = 2^s, two exps per MUFU op; results ARE the A-fragment
                const uint32_t a0 = ex2h2(f16x2_of(s0[0], s0[1]));
                const uint32_t a1 = ex2h2(f16x2_of(s0[2], s0[3]));
                const uint32_t a2 = ex2h2(f16x2_of(s1[0], s1[1]));
                const uint32_t a3 = ex2h2(f16x2_of(s1[2], s1[3]));

                // Y += P*V ; L += P*ones (row sums on tensor pipe)
                mma16816h(Y[g][0], a0, a1, a2, a3, vb0, vb1);
                mma16816h(Y[g][1], a0, a1, a2, a3, vc0, vc1);
                mma16816h(L[g],    a0, a1, a2, a3, ones, ones);
            }
        }
    }

    // ---- ones-mma left full row sums in col 0 (lanes with lane%4==0) ----
    const int h  = bh & 3;
    const int bi = bh >> 2;
    const int colb = h * DH + qc;
    const int qlead = lane & ~3;       // quad leader (holds col 0)
#pragma unroll
    for (int g = 0; g < 2; g++) {
        const float l0 = __shfl_sync(0xffffffffu, L[g][0], qlead);
        const float l1 = __shfl_sync(0xffffffffu, L[g][2], qlead);
        const float inv0 = 1.0f / l0;
        const float inv1 = 1.0f / l1;
        float* y0 = g_y + ((size_t)(bi * T_SZ + q0w + g * 16 + m)) * C_SZ + colb;
        float* y1 = y0 + 8 * C_SZ;
        *(float2*)(y0)     = make_float2(Y[g][0][0] * inv0, Y[g][0][1] * inv0);
        *(float2*)(y0 + 8) = make_float2(Y[g][1][0] * inv0, Y[g][1][1] * inv0);
        *(float2*)(y1)     = make_float2(Y[g][0][2] * inv1, Y[g][0][3] * inv1);
        *(float2*)(y1 + 8) = make_float2(Y[g][1][2] * inv1, Y[g][1][3] * inv1);
    }
}

// ==================== Kernel 3: output projection (f32x2) ===============
// 256 threads, 32 rows/block; y tile staged through smem.
__global__ void __launch_bounds__(256) proj_kernel(
    const float* __restrict__ w, const float* __restrict__ b,
    float* __restrict__ out)
{
    __shared__ float4 sw4[16 * 64];    // 16KB
    __shared__ float4 sx4[32 * 16];    // 8KB: [r][k4]
    const int t = threadIdx.x;

    const float4* w4 = (const float4*)w;
    for (int idx = t; idx < 64 * 16; idx += 256) {
        int c = idx >> 4, k4 = idx & 15;
        sw4[k4 * 64 + c] = w4[idx];
    }
    const float4* x4 = (const float4*)g_y + blockIdx.x * 512;   // 32 rows x 16 f4
    for (int idx = t; idx < 512; idx += 256) sx4[idx] = x4[idx];
    __syncthreads();

    const int col  = t & 63;
    const int rg   = t >> 6;
    const int row0 = blockIdx.x * 32 + rg * 8;
    const float bias = b[col];

    unsigned long long acc2[8];
#pragma unroll
    for (int r = 0; r < 8; r++) acc2[r] = 0ull;

#pragma unroll 4
    for (int k4 = 0; k4 < 16; k4++) {
        const float4 wv = sw4[k4 * 64 + col];
        const unsigned long long w01 = pack2(wv.x, wv.y);
        const unsigned long long w23 = pack2(wv.z, wv.w);
#pragma unroll
        for (int r = 0; r < 8; r++) {
            const float4 xv = sx4[(rg * 8 + r) * 16 + k4];   // LDS broadcast
            acc2[r] = fma2(pack2(xv.x, xv.y), w01, acc2[r]);
            acc2[r] = fma2(pack2(xv.z, xv.w), w23, acc2[r]);
        }
    }

#pragma unroll
    for (int r = 0; r < 8; r++) {
        float lo, hi;
        unpack2(acc2[r], lo, hi);
        out[(row0 + r) * 64 + col] = lo + hi + bias;
    }
}

// ==================== launch ====================
extern "C" void kernel_launch(void* const* d_in, const int* in_sizes, int n_in,
                              void* d_out, int out_size)
{
    const float* x      = (const float*)d_in[0];  // [2,4096,64]
    const float* w_attn = (const float*)d_in[1];  // [192,64]
    const float* b_attn = (const float*)d_in[2];  // [192]
    const float* w_proj = (const float*)d_in[3];  // [64,64]
    const float* b_proj = (const float*)d_in[4];  // [64]
    float* out = (float*)d_out;                   // [2,4096,64]

    dim3 qg(ROWS / 16, 2);
    qkv_kernel<<<qg, 192>>>(x, w_attn, b_attn);

    dim3 ag(T_SZ / QBLK, BH);   // (32, 8) blocks of 128 threads
    attn_kernel<<<ag, 128>>>();

    proj_kernel<<<ROWS / 32, 256>>>(w_proj, b_proj, out);
}

// round 13
// speedup vs baseline: 6.9154x; 1.3811x over previous
#include <cuda_runtime.h>
#include <cuda_bf16.h>
#include <cuda_fp16.h>
#include <cstdint>

// Problem constants: B=2, T=4096, C=64, H=4, Dh=16
#define B_SZ 2
#define T_SZ 4096
#define C_SZ 64
#define H_SZ 4
#define DH 16
#define BH (B_SZ * H_SZ)          // 8
#define ROWS (B_SZ * T_SZ)        // 8192

// softmax scale (1/sqrt(16)) * log2(e), folded into q before quantization
#define QSCALE 0.360673760222241f

#define TK 128                    // keys per tile
#define QBLK 128                  // queries per block (4 warps x 32)
#define NSPLIT 4
#define KSPAN (T_SZ / NSPLIT)     // 1024 keys per split
#define NTS (KSPAN / TK)          // 8 tiles per split

// smem row strides (fp16 units), conflict-free fragment LDS
#define KSTRIDE 24                // 16 data + 8 pad (48B rows)
#define VSTRIDE 136               // 128 data + 8 pad (272B rows)

// -------- scratch (allocation-free rule: __device__ globals) --------
__device__ __align__(32) __half g_qh[BH * T_SZ * DH];  // q*QSCALE (fp16)
__device__ __align__(32) __half g_kh[BH * T_SZ * DH];  // k (fp16)
__device__ __align__(32) __half g_vt[BH * DH * T_SZ];  // v transposed [bh][d][t]
__device__ float g_y[ROWS * C_SZ];                     // attention out
// split-K partials (unnormalized; no max-sub -> combine by pure addition)
__device__ float g_pY[NSPLIT][BH * T_SZ * DH];
__device__ float g_pL[NSPLIT][BH * T_SZ];

// ---------------- f32x2 packed-math helpers (projections) ----------------
__device__ __forceinline__ unsigned long long pack2(float lo, float hi) {
    unsigned long long r;
    asm("mov.b64 %0, {%1, %2};" : "=l"(r) : "f"(lo), "f"(hi));
    return r;
}
__device__ __forceinline__ void unpack2(unsigned long long v, float& lo, float& hi) {
    asm("mov.b64 {%0, %1}, %2;" : "=f"(lo), "=f"(hi) : "l"(v));
}
__device__ __forceinline__ unsigned long long fma2(unsigned long long a,
                                                   unsigned long long b,
                                                   unsigned long long c) {
    unsigned long long d;
    asm("fma.rn.f32x2 %0, %1, %2, %3;" : "=l"(d) : "l"(a), "l"(b), "l"(c));
    return d;
}

// ---------------- fp16 attention helpers ----------------
__device__ __forceinline__ uint32_t f16x2_of(float lo, float hi) {
    uint32_t r;
    asm("cvt.rn.f16x2.f32 %0, %1, %2;" : "=r"(r) : "f"(hi), "f"(lo));
    return r;
}
__device__ __forceinline__ uint32_t ex2h2(uint32_t s) {
    uint32_t d;
    asm("ex2.approx.f16x2 %0, %1;" : "=r"(d) : "r"(s));
    return d;
}

// mma.sync m16n8k16 row.col f32.f16.f16.f32, accumulating in place
__device__ __forceinline__ void mma16816h(float c[4],
                                          uint32_t a0, uint32_t a1,
                                          uint32_t a2, uint32_t a3,
                                          uint32_t b0, uint32_t b1) {
    asm("mma.sync.aligned.m16n8k16.row.col.f32.f16.f16.f32 "
        "{%0,%1,%2,%3}, {%4,%5,%6,%7}, {%8,%9}, {%0,%1,%2,%3};"
        : "+f"(c[0]), "+f"(c[1]), "+f"(c[2]), "+f"(c[3])
        : "r"(a0), "r"(a1), "r"(a2), "r"(a3), "r"(b0), "r"(b1));
}

// ==================== Kernel 1: fused QKV projection ====================
// Grid (ROWS/32, 2): 32 rows x 96 cols per block; weight tile staged once
// and reused over two 16-row batches. 192 threads = 96 cols x 2 row-groups.
__global__ void __launch_bounds__(192) qkv_kernel(
    const float* __restrict__ x, const float* __restrict__ w,
    const float* __restrict__ b)
{
    __shared__ float4 sw4[16 * 96];    // [k4][c96]  24KB
    __shared__ float4 sx4[32 * 16];    // [r][k4]    8KB
    const int t = threadIdx.x;
    const int chalf = blockIdx.y;

    const float4* w4 = (const float4*)w;          // w4[c*16 + k4]
    for (int idx = t; idx < 96 * 16; idx += 192) {
        int c = idx >> 4, k4 = idx & 15;
        sw4[k4 * 96 + c] = w4[(chalf * 96 + c) * 16 + k4];
    }
    const float4* x4 = (const float4*)x + blockIdx.x * 512;   // 32 rows x 16 f4
    for (int idx = t; idx < 512; idx += 192) sx4[idx] = x4[idx];
    __syncthreads();

    const int cl  = t % 96;            // local col
    const int rg  = t / 96;            // row group 0/1
    const int col = chalf * 96 + cl;   // global col 0..191
    const float bias = b[col];

    const int which = col >> 6;        // 0=q, 1=k, 2=v
    const int cc    = col & 63;
    const int h     = cc >> 4;
    const int d     = cc & 15;

#pragma unroll
    for (int rb = 0; rb < 2; rb++) {
        const int rbase = rb * 16 + rg * 8;        // row offset in tile
        const int row0  = blockIdx.x * 32 + rbase;

        unsigned long long acc2[8];
#pragma unroll
        for (int r = 0; r < 8; r++) acc2[r] = 0ull;

#pragma unroll 4
        for (int k4 = 0; k4 < 16; k4++) {
            const float4 wv = sw4[k4 * 96 + cl];
            const unsigned long long w01 = pack2(wv.x, wv.y);
            const unsigned long long w23 = pack2(wv.z, wv.w);
#pragma unroll
            for (int r = 0; r < 8; r++) {
                const float4 xv = sx4[(rbase + r) * 16 + k4];   // LDS broadcast
                acc2[r] = fma2(pack2(xv.x, xv.y), w01, acc2[r]);
                acc2[r] = fma2(pack2(xv.z, xv.w), w23, acc2[r]);
            }
        }

#pragma unroll
        for (int r = 0; r < 8; r++) {
            const int row = row0 + r;
            const int bi  = row >> 12;
            const int ti  = row & 4095;
            const int bh  = bi * H_SZ + h;
            float lo, hi;
            unpack2(acc2[r], lo, hi);
            const float val = lo + hi + bias;
            if (which == 0)
                g_qh[(bh * T_SZ + ti) * DH + d] = __float2half(val * QSCALE);
            else if (which == 1)
                g_kh[(bh * T_SZ + ti) * DH + d] = __float2half(val);
            else
                g_vt[(bh * DH + d) * T_SZ + ti] = __float2half(val);
        }
    }
}

// ============== Kernel 2: fp16 mma.sync flash attention (split-K) =======
// Grid (T/128, BH, NSPLIT), 128 threads (4 warps x 32 queries).
// S = Q*K (fp16, fp32 acc); p = ex2.f16x2(S) -> PV A-fragment directly;
// row sums via ones-column mma. Emits unnormalized partials (pure-add merge).
__global__ void __launch_bounds__(128) attn_kernel()
{
    __shared__ __half sKh[TK * KSTRIDE];   // 6 KB
    __shared__ __half sVT[DH * VSTRIDE];   // 4.25 KB

    const int tid  = threadIdx.x;
    const int warp = tid >> 5;
    const int lane = tid & 31;
    const int bh   = blockIdx.y;
    const int sp   = blockIdx.z;
    const int q0w  = blockIdx.x * QBLK + warp * 32;   // this warp's 32 queries
    const int m    = lane >> 2;        // 0..7 (row group)
    const int qc   = (lane & 3) * 2;   // 0,2,4,6 (col pair)

    // ones-column B fragment (col 0 = 1.0): lanes 0-3 hold the k rows of col 0
    const uint32_t ones = (lane < 4) ? 0x3C003C00u : 0u;

    // ---- Q fragments for 2 query groups, loaded once ----
    uint32_t qf[2][4];
#pragma unroll
    for (int g = 0; g < 2; g++) {
        const size_t r0 = ((size_t)(bh * T_SZ + q0w + g * 16 + m)) * DH + qc;
        const size_t r1 = r0 + 8 * DH;
        qf[g][0] = *(const uint32_t*)(g_qh + r0);
        qf[g][1] = *(const uint32_t*)(g_qh + r1);
        qf[g][2] = *(const uint32_t*)(g_qh + r0 + 8);
        qf[g][3] = *(const uint32_t*)(g_qh + r1 + 8);
    }

    float Y[2][2][4];           // [qgroup][d-half][frag]
    float L[2][4];              // [qgroup][frag] — ones-mma row sums
#pragma unroll
    for (int g = 0; g < 2; g++) {
#pragma unroll
        for (int i = 0; i < 4; i++) { Y[g][0][i] = 0.f; Y[g][1][i] = 0.f; L[g][i] = 0.f; }
    }

    const __half* khb = g_kh + (size_t)bh * T_SZ * DH + (size_t)sp * KSPAN * DH;
    const __half* vtb = g_vt + (size_t)bh * DH * T_SZ + sp * KSPAN;

    const int vrow = tid >> 3, vchunk = tid & 7;   // V coop: 16 rows x 8 chunks

    for (int nt = 0; nt < NTS; nt++) {
        const int kt = nt * TK;
        __syncthreads();
        // ---- cooperative tile load ----
        {
            const uint4* sh = (const uint4*)(khb + (size_t)(kt + tid) * DH);
            uint4* dh = (uint4*)(sKh + tid * KSTRIDE);
            dh[0] = sh[0];
            dh[1] = sh[1];
            const uint4* vs = (const uint4*)(vtb + (size_t)vrow * T_SZ + kt + vchunk * 16);
            uint4* vd = (uint4*)(sVT + vrow * VSTRIDE + vchunk * 16);
            vd[0] = vs[0];
            vd[1] = vs[1];
        }
        __syncthreads();

#pragma unroll 2
        for (int st = 0; st < 8; st++) {
            const int key0 = st * 16;
            const __half* kp0 = sKh + (key0 + m) * KSTRIDE + qc;
            const __half* kp1 = kp0 + 8 * KSTRIDE;
            const uint32_t b00 = *(const uint32_t*)kp0;
            const uint32_t b01 = *(const uint32_t*)(kp0 + 8);
            const uint32_t b10 = *(const uint32_t*)kp1;
            const uint32_t b11 = *(const uint32_t*)(kp1 + 8);
            const __half* vp = sVT + m * VSTRIDE + key0 + qc;
            const uint32_t vb0 = *(const uint32_t*)vp;
            const uint32_t vb1 = *(const uint32_t*)(vp + 8);
            const uint32_t vc0 = *(const uint32_t*)(vp + 8 * VSTRIDE);
            const uint32_t vc1 = *(const uint32_t*)(vp + 8 * VSTRIDE + 8);

#pragma unroll
            for (int g = 0; g < 2; g++) {
                float s0[4] = {0.f, 0.f, 0.f, 0.f};
                float s1[4] = {0.f, 0.f, 0.f, 0.f};
                mma16816h(s0, qf[g][0], qf[g][1], qf[g][2], qf[g][3], b00, b01);
                mma16816h(s1, qf[g][0], qf[g][1], qf[g][2], qf[g][3], b10, b11);

                const uint32_t a0 = ex2h2(f16x2_of(s0[0], s0[1]));
                const uint32_t a1 = ex2h2(f16x2_of(s0[2], s0[3]));
                const uint32_t a2 = ex2h2(f16x2_of(s1[0], s1[1]));
                const uint32_t a3 = ex2h2(f16x2_of(s1[2], s1[3]));

                mma16816h(Y[g][0], a0, a1, a2, a3, vb0, vb1);
                mma16816h(Y[g][1], a0, a1, a2, a3, vc0, vc1);
                mma16816h(L[g],    a0, a1, a2, a3, ones, ones);
            }
        }
    }

    // ---- emit unnormalized partials ----
    float* pY = g_pY[sp];
    float* pL = g_pL[sp];
#pragma unroll
    for (int g = 0; g < 2; g++) {
        const size_t r0 = (size_t)(bh * T_SZ + q0w + g * 16 + m);
        const size_t r1 = r0 + 8;
        *(float2*)(pY + r0 * DH + qc)     = make_float2(Y[g][0][0], Y[g][0][1]);
        *(float2*)(pY + r0 * DH + qc + 8) = make_float2(Y[g][1][0], Y[g][1][1]);
        *(float2*)(pY + r1 * DH + qc)     = make_float2(Y[g][0][2], Y[g][0][3]);
        *(float2*)(pY + r1 * DH + qc + 8) = make_float2(Y[g][1][2], Y[g][1][3]);
        if ((lane & 3) == 0) {             // quad leader holds col-0 row sums
            pL[r0] = L[g][0];
            pL[r1] = L[g][2];
        }
    }
}

// ==================== Kernel 2b: split-K merge (pure add) ===============
__global__ void __launch_bounds__(128) merge_kernel()
{
    const int qi = blockIdx.x * 128 + threadIdx.x;   // bh*T + ti
    const int bh = qi >> 12;
    const int ti = qi & 4095;

    float l = 0.f;
#pragma unroll
    for (int s = 0; s < NSPLIT; s++) l += g_pL[s][qi];
    const float inv = 1.0f / l;

    float4 a0 = make_float4(0.f, 0.f, 0.f, 0.f);
    float4 a1 = a0, a2 = a0, a3 = a0;
#pragma unroll
    for (int s = 0; s < NSPLIT; s++) {
        const float4* p = (const float4*)(g_pY[s] + (size_t)qi * DH);
        float4 f0 = p[0], f1 = p[1], f2 = p[2], f3 = p[3];
        a0.x += f0.x; a0.y += f0.y; a0.z += f0.z; a0.w += f0.w;
        a1.x += f1.x; a1.y += f1.y; a1.z += f1.z; a1.w += f1.w;
        a2.x += f2.x; a2.y += f2.y; a2.z += f2.z; a2.w += f2.w;
        a3.x += f3.x; a3.y += f3.y; a3.z += f3.z; a3.w += f3.w;
    }

    const int h  = bh & 3;
    const int bi = bh >> 2;
    float4* yp = (float4*)(g_y + (size_t)(bi * T_SZ + ti) * C_SZ + h * DH);
    yp[0] = make_float4(a0.x * inv, a0.y * inv, a0.z * inv, a0.w * inv);
    yp[1] = make_float4(a1.x * inv, a1.y * inv, a1.z * inv, a1.w * inv);
    yp[2] = make_float4(a2.x * inv, a2.y * inv, a2.z * inv, a2.w * inv);
    yp[3] = make_float4(a3.x * inv, a3.y * inv, a3.z * inv, a3.w * inv);
}

// ==================== Kernel 3: output projection (f32x2) ===============
__global__ void __launch_bounds__(256) proj_kernel(
    const float* __restrict__ w, const float* __restrict__ b,
    float* __restrict__ out)
{
    __shared__ float4 sw4[16 * 64];    // 16KB
    __shared__ float4 sx4[32 * 16];    // 8KB: [r][k4]
    const int t = threadIdx.x;

    const float4* w4 = (const float4*)w;
    for (int idx = t; idx < 64 * 16; idx += 256) {
        int c = idx >> 4, k4 = idx & 15;
        sw4[k4 * 64 + c] = w4[idx];
    }
    const float4* x4 = (const float4*)g_y + blockIdx.x * 512;   // 32 rows x 16 f4
    for (int idx = t; idx < 512; idx += 256) sx4[idx] = x4[idx];
    __syncthreads();

    const int col  = t & 63;
    const int rg   = t >> 6;
    const int row0 = blockIdx.x * 32 + rg * 8;
    const float bias = b[col];

    unsigned long long acc2[8];
#pragma unroll
    for (int r = 0; r < 8; r++) acc2[r] = 0ull;

#pragma unroll 4
    for (int k4 = 0; k4 < 16; k4++) {
        const float4 wv = sw4[k4 * 64 + col];
        const unsigned long long w01 = pack2(wv.x, wv.y);
        const unsigned long long w23 = pack2(wv.z, wv.w);
#pragma unroll
        for (int r = 0; r < 8; r++) {
            const float4 xv = sx4[(rg * 8 + r) * 16 + k4];   // LDS broadcast
            acc2[r] = fma2(pack2(xv.x, xv.y), w01, acc2[r]);
            acc2[r] = fma2(pack2(xv.z, xv.w), w23, acc2[r]);
        }
    }

#pragma unroll
    for (int r = 0; r < 8; r++) {
        float lo, hi;
        unpack2(acc2[r], lo, hi);
        out[(row0 + r) * 64 + col] = lo + hi + bias;
    }
}

// ==================== launch ====================
extern "C" void kernel_launch(void* const* d_in, const int* in_sizes, int n_in,
                              void* d_out, int out_size)
{
    const float* x      = (const float*)d_in[0];  // [2,4096,64]
    const float* w_attn = (const float*)d_in[1];  // [192,64]
    const float* b_attn = (const float*)d_in[2];  // [192]
    const float* w_proj = (const float*)d_in[3];  // [64,64]
    const float* b_proj = (const float*)d_in[4];  // [64]
    float* out = (float*)d_out;                   // [2,4096,64]

    dim3 qg(ROWS / 32, 2);
    qkv_kernel<<<qg, 192>>>(x, w_attn, b_attn);

    dim3 ag(T_SZ / QBLK, BH, NSPLIT);   // (32, 8, 4) blocks of 128 threads
    attn_kernel<<<ag, 128>>>();

    merge_kernel<<<(BH * T_SZ) / 128, 128>>>();

    proj_kernel<<<ROWS / 32, 256>>>(w_proj, b_proj, out);
}

// round 14
// speedup vs baseline: 7.1909x; 1.0398x over previous
#include <cuda_runtime.h>
#include <cuda_bf16.h>
#include <cuda_fp16.h>
#include <cstdint>

// Problem constants: B=2, T=4096, C=64, H=4, Dh=16
#define B_SZ 2
#define T_SZ 4096
#define C_SZ 64
#define H_SZ 4
#define DH 16
#define BH (B_SZ * H_SZ)          // 8
#define ROWS (B_SZ * T_SZ)        // 8192

// softmax scale (1/sqrt(16)) * log2(e), folded into q before quantization
#define QSCALE 0.360673760222241f

#define TK 128                    // keys per tile
#define QBLK 128                  // queries per block (4 warps x 32)
#define NSPLIT 4
#define KSPAN (T_SZ / NSPLIT)     // 1024 keys per split
#define NTS (KSPAN / TK)          // 8 tiles per split

// smem row strides (fp16 units), conflict-free fragment LDS / LDSM
#define KSTRIDE 24                // 16 data + 8 pad (48B rows; 12i mod 32 distinct)
#define VSTRIDE 136               // 128 data + 8 pad (272B rows; 4i mod 32 distinct)

// -------- scratch (allocation-free rule: __device__ globals) --------
__device__ __align__(32) __half g_qh[BH * T_SZ * DH];  // q*QSCALE (fp16)
__device__ __align__(32) __half g_kh[BH * T_SZ * DH];  // k (fp16)
__device__ __align__(32) __half g_vt[BH * DH * T_SZ];  // v transposed [bh][d][t]
// split-K partials (unnormalized; no max-sub -> combine by pure addition)
__device__ float g_pY[NSPLIT][BH * T_SZ * DH];
__device__ float g_pL[NSPLIT][BH * T_SZ];

// ---------------- f32x2 packed-math helpers (projections) ----------------
__device__ __forceinline__ void unpack2(unsigned long long v, float& lo, float& hi) {
    asm("mov.b64 {%0, %1}, %2;" : "=f"(lo), "=f"(hi) : "l"(v));
}
__device__ __forceinline__ unsigned long long fma2(unsigned long long a,
                                                   unsigned long long b,
                                                   unsigned long long c) {
    unsigned long long d;
    asm("fma.rn.f32x2 %0, %1, %2, %3;" : "=l"(d) : "l"(a), "l"(b), "l"(c));
    return d;
}

// ---------------- fp16 attention helpers ----------------
__device__ __forceinline__ uint32_t f16x2_of(float lo, float hi) {
    uint32_t r;
    asm("cvt.rn.f16x2.f32 %0, %1, %2;" : "=r"(r) : "f"(hi), "f"(lo));
    return r;
}
__device__ __forceinline__ uint32_t ex2h2(uint32_t s) {
    uint32_t d;
    asm("ex2.approx.f16x2 %0, %1;" : "=r"(d) : "r"(s));
    return d;
}
__device__ __forceinline__ uint32_t smem_u32(const void* p) {
    uint32_t a;
    asm("{ .reg .u64 t; cvta.to.shared.u64 t, %1; cvt.u32.u64 %0, t; }"
        : "=r"(a) : "l"(p));
    return a;
}
// ldmatrix m8n8.x4 (non-trans, b16): 4 fragments in one op
__device__ __forceinline__ void ldmx4(uint32_t& r0, uint32_t& r1,
                                      uint32_t& r2, uint32_t& r3, uint32_t a) {
    asm volatile("ldmatrix.sync.aligned.m8n8.x4.shared.b16 {%0,%1,%2,%3}, [%4];"
                 : "=r"(r0), "=r"(r1), "=r"(r2), "=r"(r3) : "r"(a));
}

// mma.sync m16n8k16 row.col f32.f16.f16.f32, accumulating in place
__device__ __forceinline__ void mma16816h(float c[4],
                                          uint32_t a0, uint32_t a1,
                                          uint32_t a2, uint32_t a3,
                                          uint32_t b0, uint32_t b1) {
    asm("mma.sync.aligned.m16n8k16.row.col.f32.f16.f16.f32 "
        "{%0,%1,%2,%3}, {%4,%5,%6,%7}, {%8,%9}, {%0,%1,%2,%3};"
        : "+f"(c[0]), "+f"(c[1]), "+f"(c[2]), "+f"(c[3])
        : "r"(a0), "r"(a1), "r"(a2), "r"(a3), "r"(b0), "r"(b1));
}

// ==================== Kernel 1: fused QKV projection ====================
// Grid (ROWS/32, 2): 32 rows x 96 cols per block. Operands staged in smem
// as pre-packed f32x2 pairs (ulonglong2) -> zero pack MOVs in the hot loop.
__global__ void __launch_bounds__(192) qkv_kernel(
    const float* __restrict__ x, const float* __restrict__ w,
    const float* __restrict__ b)
{
    __shared__ ulonglong2 sw2[16 * 96];    // [k4][c96]  24KB
    __shared__ ulonglong2 sx2[32 * 16];    // [r][k4]    8KB
    const int t = threadIdx.x;
    const int chalf = blockIdx.y;

    const ulonglong2* w2 = (const ulonglong2*)w;    // w2[c*16 + k4]
    for (int idx = t; idx < 96 * 16; idx += 192) {
        int c = idx >> 4, k4 = idx & 15;
        sw2[k4 * 96 + c] = w2[(chalf * 96 + c) * 16 + k4];
    }
    const ulonglong2* x2 = (const ulonglong2*)x + blockIdx.x * 512;
    for (int idx = t; idx < 512; idx += 192) sx2[idx] = x2[idx];
    __syncthreads();

    const int cl  = t % 96;
    const int rg  = t / 96;
    const int col = chalf * 96 + cl;
    const float bias = b[col];

    const int which = col >> 6;        // 0=q, 1=k, 2=v
    const int cc    = col & 63;
    const int h     = cc >> 4;
    const int d     = cc & 15;

#pragma unroll
    for (int rb = 0; rb < 2; rb++) {
        const int rbase = rb * 16 + rg * 8;
        const int row0  = blockIdx.x * 32 + rbase;

        unsigned long long acc2[8];
#pragma unroll
        for (int r = 0; r < 8; r++) acc2[r] = 0ull;

#pragma unroll 4
        for (int k4 = 0; k4 < 16; k4++) {
            const ulonglong2 wv = sw2[k4 * 96 + cl];
#pragma unroll
            for (int r = 0; r < 8; r++) {
                const ulonglong2 xv = sx2[(rbase + r) * 16 + k4];  // LDS.128
                acc2[r] = fma2(xv.x, wv.x, acc2[r]);
                acc2[r] = fma2(xv.y, wv.y, acc2[r]);
            }
        }

#pragma unroll
        for (int r = 0; r < 8; r++) {
            const int row = row0 + r;
            const int bi  = row >> 12;
            const int ti  = row & 4095;
            const int bh  = bi * H_SZ + h;
            float lo, hi;
            unpack2(acc2[r], lo, hi);
            const float val = lo + hi + bias;
            if (which == 0)
                g_qh[(bh * T_SZ + ti) * DH + d] = __float2half(val * QSCALE);
            else if (which == 1)
                g_kh[(bh * T_SZ + ti) * DH + d] = __float2half(val);
            else
                g_vt[(bh * DH + d) * T_SZ + ti] = __float2half(val);
        }
    }
}

// ============== Kernel 2: fp16 mma.sync flash attention (split-K) =======
// Grid (T/128, BH, NSPLIT), 128 threads (4 warps x 32 queries).
// K/V fragments via ldmatrix.x4; S = Q*K (fp32 acc); p = ex2.f16x2(S) ->
// PV A-fragment directly; row sums via ones-column mma. Emits unnormalized
// partials (pure-add merge in proj).
__global__ void __launch_bounds__(128) attn_kernel()
{
    __shared__ __half sKh[TK * KSTRIDE];   // 6 KB
    __shared__ __half sVT[DH * VSTRIDE];   // 4.25 KB

    const int tid  = threadIdx.x;
    const int warp = tid >> 5;
    const int lane = tid & 31;
    const int bh   = blockIdx.y;
    const int sp   = blockIdx.z;
    const int q0w  = blockIdx.x * QBLK + warp * 32;
    const int m    = lane >> 2;        // 0..7 (row group)
    const int qc   = (lane & 3) * 2;   // 0,2,4,6 (col pair)

    // ones-column B fragment (col 0 = 1.0): lanes 0-3 hold the k rows of col 0
    const uint32_t ones = (lane < 4) ? 0x3C003C00u : 0u;

    // ldmatrix per-thread source addresses (4 matrices per op)
    const int li = lane & 7;
    const int hi8  = (lane >> 4) & 1;   // matrices 2,3
    const int c16  = (lane >> 3) & 1;   // matrices 1,3
    const uint32_t k_sm = smem_u32(sKh) + (uint32_t)((li + hi8 * 8) * (KSTRIDE * 2) + c16 * 16);
    const uint32_t v_sm = smem_u32(sVT) + (uint32_t)((li + hi8 * 8) * (VSTRIDE * 2) + c16 * 16);

    // ---- Q fragments for 2 query groups, loaded once ----
    uint32_t qf[2][4];
#pragma unroll
    for (int g = 0; g < 2; g++) {
        const size_t r0 = ((size_t)(bh * T_SZ + q0w + g * 16 + m)) * DH + qc;
        const size_t r1 = r0 + 8 * DH;
        qf[g][0] = *(const uint32_t*)(g_qh + r0);
        qf[g][1] = *(const uint32_t*)(g_qh + r1);
        qf[g][2] = *(const uint32_t*)(g_qh + r0 + 8);
        qf[g][3] = *(const uint32_t*)(g_qh + r1 + 8);
    }

    float Y[2][2][4];
    float L[2][4];
#pragma unroll
    for (int g = 0; g < 2; g++) {
#pragma unroll
        for (int i = 0; i < 4; i++) { Y[g][0][i] = 0.f; Y[g][1][i] = 0.f; L[g][i] = 0.f; }
    }

    const __half* khb = g_kh + (size_t)bh * T_SZ * DH + (size_t)sp * KSPAN * DH;
    const __half* vtb = g_vt + (size_t)bh * DH * T_SZ + sp * KSPAN;

    const int vrow = tid >> 3, vchunk = tid & 7;

    for (int nt = 0; nt < NTS; nt++) {
        const int kt = nt * TK;
        __syncthreads();
        {
            const uint4* sh = (const uint4*)(khb + (size_t)(kt + tid) * DH);
            uint4* dh = (uint4*)(sKh + tid * KSTRIDE);
            dh[0] = sh[0];
            dh[1] = sh[1];
            const uint4* vs = (const uint4*)(vtb + (size_t)vrow * T_SZ + kt + vchunk * 16);
            uint4* vd = (uint4*)(sVT + vrow * VSTRIDE + vchunk * 16);
            vd[0] = vs[0];
            vd[1] = vs[1];
        }
        __syncthreads();

#pragma unroll 2
        for (int st = 0; st < 8; st++) {
            uint32_t b00, b01, b10, b11;
            ldmx4(b00, b01, b10, b11, k_sm + (uint32_t)(st * 16 * KSTRIDE * 2));
            uint32_t vb0, vb1, vc0, vc1;
            ldmx4(vb0, vb1, vc0, vc1, v_sm + (uint32_t)(st * 32));

#pragma unroll
            for (int g = 0; g < 2; g++) {
                float s0[4] = {0.f, 0.f, 0.f, 0.f};
                float s1[4] = {0.f, 0.f, 0.f, 0.f};
                mma16816h(s0, qf[g][0], qf[g][1], qf[g][2], qf[g][3], b00, b01);
                mma16816h(s1, qf[g][0], qf[g][1], qf[g][2], qf[g][3], b10, b11);

                const uint32_t a0 = ex2h2(f16x2_of(s0[0], s0[1]));
                const uint32_t a1 = ex2h2(f16x2_of(s0[2], s0[3]));
                const uint32_t a2 = ex2h2(f16x2_of(s1[0], s1[1]));
                const uint32_t a3 = ex2h2(f16x2_of(s1[2], s1[3]));

                mma16816h(Y[g][0], a0, a1, a2, a3, vb0, vb1);
                mma16816h(Y[g][1], a0, a1, a2, a3, vc0, vc1);
                mma16816h(L[g],    a0, a1, a2, a3, ones, ones);
            }
        }
    }

    // ---- emit unnormalized partials ----
    float* pY = g_pY[sp];
    float* pL = g_pL[sp];
#pragma unroll
    for (int g = 0; g < 2; g++) {
        const size_t r0 = (size_t)(bh * T_SZ + q0w + g * 16 + m);
        const size_t r1 = r0 + 8;
        *(float2*)(pY + r0 * DH + qc)     = make_float2(Y[g][0][0], Y[g][0][1]);
        *(float2*)(pY + r0 * DH + qc + 8) = make_float2(Y[g][1][0], Y[g][1][1]);
        *(float2*)(pY + r1 * DH + qc)     = make_float2(Y[g][0][2], Y[g][0][3]);
        *(float2*)(pY + r1 * DH + qc + 8) = make_float2(Y[g][1][2], Y[g][1][3]);
        if ((lane & 3) == 0) {
            pL[r0] = L[g][0];
            pL[r1] = L[g][2];
        }
    }
}

// ========== Kernel 3: fused split-K merge + output projection ==========
// Grid ROWS/32 blocks of 256. Stage 1: sum 4 partials + normalize into smem
// (packed f32x2). Stage 2: GEMM vs w_proj.
__global__ void __launch_bounds__(256) proj_kernel(
    const float* __restrict__ w, const float* __restrict__ b,
    float* __restrict__ out)
{
    __shared__ ulonglong2 sw2[16 * 64];    // 16KB
    __shared__ ulonglong2 sx2[32 * 16];    // 8KB: y rows packed
    __shared__ float sinv[32][4];
    const int t = threadIdx.x;
    const int row0blk = blockIdx.x * 32;

    const ulonglong2* w2 = (const ulonglong2*)w;
    for (int idx = t; idx < 64 * 16; idx += 256) {
        int c = idx >> 4, k4 = idx & 15;
        sw2[k4 * 64 + c] = w2[idx];
    }

    // per-(row, head) inverse row sums
    if (t < 128) {
        const int r  = t >> 2;
        const int h  = t & 3;
        const int row = row0blk + r;
        const int bi = row >> 12, ti = row & 4095;
        const int qi = (bi * H_SZ + h) * T_SZ + ti;
        const float l = g_pL[0][qi] + g_pL[1][qi] + g_pL[2][qi] + g_pL[3][qi];
        sinv[r][h] = 1.0f / l;
    }
    __syncthreads();

    // y assembly: 32 rows x 16 float4
    for (int idx = t; idx < 512; idx += 256) {
        const int r  = idx >> 4;
        const int c4 = idx & 15;
        const int row = row0blk + r;
        const int bi = row >> 12, ti = row & 4095;
        const int h  = c4 >> 2;
        const int d4 = c4 & 3;
        const size_t pb = ((size_t)((bi * H_SZ + h) * T_SZ + ti)) * DH + d4 * 4;
        float4 a0 = *(const float4*)(g_pY[0] + pb);
        float4 a1 = *(const float4*)(g_pY[1] + pb);
        float4 a2 = *(const float4*)(g_pY[2] + pb);
        float4 a3 = *(const float4*)(g_pY[3] + pb);
        const float inv = sinv[r][h];
        float4 y;
        y.x = (a0.x + a1.x + a2.x + a3.x) * inv;
        y.y = (a0.y + a1.y + a2.y + a3.y) * inv;
        y.z = (a0.z + a1.z + a2.z + a3.z) * inv;
        y.w = (a0.w + a1.w + a2.w + a3.w) * inv;
        *(float4*)&sx2[r * 16 + c4] = y;
    }
    __syncthreads();

    const int col  = t & 63;
    const int rg   = t >> 6;
    const int row0 = row0blk + rg * 8;
    const float bias = b[col];

    unsigned long long acc2[8];
#pragma unroll
    for (int r = 0; r < 8; r++) acc2[r] = 0ull;

#pragma unroll 4
    for (int k4 = 0; k4 < 16; k4++) {
        const ulonglong2 wv = sw2[k4 * 64 + col];
#pragma unroll
        for (int r = 0; r < 8; r++) {
            const ulonglong2 xv = sx2[(rg * 8 + r) * 16 + k4];
            acc2[r] = fma2(xv.x, wv.x, acc2[r]);
            acc2[r] = fma2(xv.y, wv.y, acc2[r]);
        }
    }

#pragma unroll
    for (int r = 0; r < 8; r++) {
        float lo, hi;
        unpack2(acc2[r], lo, hi);
        out[(row0 + r) * 64 + col] = lo + hi + bias;
    }
}

// ==================== launch ====================
extern "C" void kernel_launch(void* const* d_in, const int* in_sizes, int n_in,
                              void* d_out, int out_size)
{
    const float* x      = (const float*)d_in[0];  // [2,4096,64]
    const float* w_attn = (const float*)d_in[1];  // [192,64]
    const float* b_attn = (const float*)d_in[2];  // [192]
    const float* w_proj = (const float*)d_in[3];  // [64,64]
    const float* b_proj = (const float*)d_in[4];  // [64]
    float* out = (float*)d_out;                   // [2,4096,64]

    dim3 qg(ROWS / 32, 2);
    qkv_kernel<<<qg, 192>>>(x, w_attn, b_attn);

    dim3 ag(T_SZ / QBLK, BH, NSPLIT);   // (32, 8, 4) blocks of 128 threads
    attn_kernel<<<ag, 128>>>();

    proj_kernel<<<ROWS / 32, 256>>>(w_proj, b_proj, out);
}

// round 15
// speedup vs baseline: 9.1314x; 1.2699x over previous
#include <cuda_runtime.h>
#include <cuda_bf16.h>
#include <cuda_fp16.h>
#include <cstdint>

// Problem constants: B=2, T=4096, C=64, H=4, Dh=16
#define B_SZ 2
#define T_SZ 4096
#define C_SZ 64
#define H_SZ 4
#define DH 16
#define BH (B_SZ * H_SZ)          // 8
#define ROWS (B_SZ * T_SZ)        // 8192

// softmax scale (1/sqrt(16)) * log2(e), folded into q before quantization
#define QSCALE 0.360673760222241f

#define TK 128                    // keys per tile
#define QBLK 128                  // queries per block (4 warps x 32)
#define NSPLIT 4
#define KSPAN (T_SZ / NSPLIT)     // 1024 keys per split
#define NTS (KSPAN / TK)          // 8 tiles per split

// smem row strides (fp16 units), conflict-free fragment LDS / LDSM
#define KSTRIDE 24                // 16 data + 8 pad (48B rows)
#define VSTRIDE 136               // 128 data + 8 pad (272B rows)
#define XSTRIDE 72                // 64 data + 8 pad (144B rows; 16i mod 128 distinct)

// -------- scratch (allocation-free rule: __device__ globals) --------
__device__ __align__(32) __half g_qh[BH * T_SZ * DH];  // q*QSCALE (fp16)
__device__ __align__(32) __half g_kh[BH * T_SZ * DH];  // k (fp16)
__device__ __align__(32) __half g_vt[BH * DH * T_SZ];  // v transposed [bh][d][t]
// split-K partials (unnormalized; no max-sub -> combine by pure addition)
__device__ float g_pY[NSPLIT][BH * T_SZ * DH];
__device__ float g_pL[NSPLIT][BH * T_SZ];

// ---------------- f32x2 packed-math helpers (projections) ----------------
__device__ __forceinline__ void unpack2(unsigned long long v, float& lo, float& hi) {
    asm("mov.b64 {%0, %1}, %2;" : "=f"(lo), "=f"(hi) : "l"(v));
}
__device__ __forceinline__ unsigned long long fma2(unsigned long long a,
                                                   unsigned long long b,
                                                   unsigned long long c) {
    unsigned long long d;
    asm("fma.rn.f32x2 %0, %1, %2, %3;" : "=l"(d) : "l"(a), "l"(b), "l"(c));
    return d;
}

// ---------------- fp16 helpers ----------------
__device__ __forceinline__ uint32_t f16x2_of(float lo, float hi) {
    uint32_t r;
    asm("cvt.rn.f16x2.f32 %0, %1, %2;" : "=r"(r) : "f"(hi), "f"(lo));
    return r;
}
__device__ __forceinline__ uint32_t ex2h2(uint32_t s) {
    uint32_t d;
    asm("ex2.approx.f16x2 %0, %1;" : "=r"(d) : "r"(s));
    return d;
}
__device__ __forceinline__ uint32_t smem_u32(const void* p) {
    uint32_t a;
    asm("{ .reg .u64 t; cvta.to.shared.u64 t, %1; cvt.u32.u64 %0, t; }"
        : "=r"(a) : "l"(p));
    return a;
}
// ldmatrix m8n8.x4 (non-trans, b16): 4 fragments in one op
__device__ __forceinline__ void ldmx4(uint32_t& r0, uint32_t& r1,
                                      uint32_t& r2, uint32_t& r3, uint32_t a) {
    asm volatile("ldmatrix.sync.aligned.m8n8.x4.shared.b16 {%0,%1,%2,%3}, [%4];"
                 : "=r"(r0), "=r"(r1), "=r"(r2), "=r"(r3) : "r"(a));
}

// mma.sync m16n8k16 row.col f32.f16.f16.f32, accumulating in place
__device__ __forceinline__ void mma16816h(float c[4],
                                          uint32_t a0, uint32_t a1,
                                          uint32_t a2, uint32_t a3,
                                          uint32_t b0, uint32_t b1) {
    asm("mma.sync.aligned.m16n8k16.row.col.f32.f16.f16.f32 "
        "{%0,%1,%2,%3}, {%4,%5,%6,%7}, {%8,%9}, {%0,%1,%2,%3};"
        : "+f"(c[0]), "+f"(c[1]), "+f"(c[2]), "+f"(c[3])
        : "r"(a0), "r"(a1), "r"(a2), "r"(a3), "r"(b0), "r"(b1));
}

// ==================== Kernel 1: tensor-core QKV projection ==============
// Grid 128 blocks x 256 threads (8 warps). Block = 64 rows x 192 cols,
// K=64. x/w converted fp32->fp16 while staging into ldmatrix-friendly smem.
// Warp = 16-row group x 96-col half: A frags held in regs; per n-tile-pair
// 4 ldmatrix.x4 (B) + 8 mma; epilogue scatters fragments into q/k/vt.
__global__ void __launch_bounds__(256) qkv_kernel(
    const float* __restrict__ x, const float* __restrict__ w,
    const float* __restrict__ b)
{
    __shared__ __half sX[64 * XSTRIDE];    // 9.2 KB
    __shared__ __half sW[192 * XSTRIDE];   // 27.6 KB
    __shared__ float sB[192];
    const int t = threadIdx.x;

    // stage W (convert fp32 -> fp16)
    const float4* w4 = (const float4*)w;          // w4[n*16 + k4]
    for (int idx = t; idx < 192 * 16; idx += 256) {
        const int n = idx >> 4, k4 = idx & 15;
        const float4 f = w4[idx];
        uint2 h;
        h.x = f16x2_of(f.x, f.y);
        h.y = f16x2_of(f.z, f.w);
        *(uint2*)(sW + n * XSTRIDE + k4 * 4) = h;
    }
    // stage X (convert fp32 -> fp16)
    const float4* x4 = (const float4*)x + (size_t)blockIdx.x * 64 * 16;
    for (int idx = t; idx < 64 * 16; idx += 256) {
        const int r = idx >> 4, k4 = idx & 15;
        const float4 f = x4[idx];
        uint2 h;
        h.x = f16x2_of(f.x, f.y);
        h.y = f16x2_of(f.z, f.w);
        *(uint2*)(sX + r * XSTRIDE + k4 * 4) = h;
    }
    if (t < 192) sB[t] = b[t];
    __syncthreads();

    const int warp = t >> 5, lane = t & 31;
    const int rg     = warp >> 1;      // row group 0..3 (16 rows each)
    const int chalfw = warp & 1;       // col half: 0 -> cols 0-95, 1 -> 96-191
    const int m_ = lane >> 2;          // 0..7
    const int qc = (lane & 3) * 2;     // 0,2,4,6
    const int li = lane & 7;
    const int c16 = (lane >> 3) & 1;
    const int hi8 = (lane >> 4) & 1;

    // A fragments: rows rg*16..+15, k=0..63 (4 ksteps)
    uint32_t a[4][4];
    {
        const uint32_t xa = smem_u32(sX)
            + (uint32_t)(((rg * 16 + li + hi8 * 8) * XSTRIDE + c16 * 8) * 2);
#pragma unroll
        for (int ks = 0; ks < 4; ks++) {
            uint32_t r0, r1, r2, r3;
            ldmx4(r0, r1, r2, r3, xa + ks * 32);
            a[ks][0] = r0; a[ks][1] = r2; a[ks][2] = r1; a[ks][3] = r3;
        }
    }

    const uint32_t wb = smem_u32(sW) + (uint32_t)(((li + hi8 * 8) * XSTRIDE + c16 * 8) * 2);
    const int row0 = blockIdx.x * 64 + rg * 16;
    const int bi   = row0 >> 12;
    const int ti0  = (row0 & 4095) + m_;

#pragma unroll
    for (int p = 0; p < 6; p++) {
        const int n0 = chalfw * 96 + p * 16;    // two n-tiles: n0, n0+8
        float c0[4] = {0.f, 0.f, 0.f, 0.f};
        float c1[4] = {0.f, 0.f, 0.f, 0.f};
#pragma unroll
        for (int ks = 0; ks < 4; ks++) {
            uint32_t b0, b1, b2, b3;
            ldmx4(b0, b1, b2, b3, wb + (uint32_t)(n0 * XSTRIDE * 2 + ks * 32));
            mma16816h(c0, a[ks][0], a[ks][1], a[ks][2], a[ks][3], b0, b1);
            mma16816h(c1, a[ks][0], a[ks][1], a[ks][2], a[ks][3], b2, b3);
        }
        // epilogue: two n-tiles
#pragma unroll
        for (int sub = 0; sub < 2; sub++) {
            float* c = sub ? c1 : c0;
            const int col0 = n0 + sub * 8;
            const float b0v = sB[col0 + qc];
            const float b1v = sB[col0 + qc + 1];
            float e0 = c[0] + b0v, e1 = c[1] + b1v;
            float e2 = c[2] + b0v, e3 = c[3] + b1v;
            const int seg = col0 >> 6;          // 0=q, 1=k, 2=v
            const int cc  = col0 & 63;
            const int h   = cc >> 4;
            const int d0  = (cc & 15) + qc;
            const int bh  = bi * H_SZ + h;
            if (seg == 0) {
                e0 *= QSCALE; e1 *= QSCALE; e2 *= QSCALE; e3 *= QSCALE;
                const size_t base = ((size_t)(bh * T_SZ + ti0)) * DH + d0;
                *(uint32_t*)(g_qh + base)          = f16x2_of(e0, e1);
                *(uint32_t*)(g_qh + base + 8 * DH) = f16x2_of(e2, e3);
            } else if (seg == 1) {
                const size_t base = ((size_t)(bh * T_SZ + ti0)) * DH + d0;
                *(uint32_t*)(g_kh + base)          = f16x2_of(e0, e1);
                *(uint32_t*)(g_kh + base + 8 * DH) = f16x2_of(e2, e3);
            } else {
                const size_t vb = ((size_t)(bh * DH + d0)) * T_SZ + ti0;
                g_vt[vb]            = __float2half(e0);
                g_vt[vb + T_SZ]     = __float2half(e1);
                g_vt[vb + 8]        = __float2half(e2);
                g_vt[vb + T_SZ + 8] = __float2half(e3);
            }
        }
    }
}

// ============== Kernel 2: fp16 mma.sync flash attention (split-K) =======
// Grid (T/128, BH, NSPLIT), 128 threads (4 warps x 32 queries).
// K/V fragments via ldmatrix.x4; S = Q*K (fp32 acc); p = ex2.f16x2(S) ->
// PV A-fragment directly; row sums via ones-column mma. Emits unnormalized
// partials (pure-add merge in proj).
__global__ void __launch_bounds__(128) attn_kernel()
{
    __shared__ __half sKh[TK * KSTRIDE];   // 6 KB
    __shared__ __half sVT[DH * VSTRIDE];   // 4.25 KB

    const int tid  = threadIdx.x;
    const int warp = tid >> 5;
    const int lane = tid & 31;
    const int bh   = blockIdx.y;
    const int sp   = blockIdx.z;
    const int q0w  = blockIdx.x * QBLK + warp * 32;
    const int m    = lane >> 2;        // 0..7 (row group)
    const int qc   = (lane & 3) * 2;   // 0,2,4,6 (col pair)

    // ones-column B fragment (col 0 = 1.0): lanes 0-3 hold the k rows of col 0
    const uint32_t ones = (lane < 4) ? 0x3C003C00u : 0u;

    // ldmatrix per-thread source addresses (4 matrices per op)
    const int li = lane & 7;
    const int hi8  = (lane >> 4) & 1;
    const int c16  = (lane >> 3) & 1;
    const uint32_t k_sm = smem_u32(sKh) + (uint32_t)((li + hi8 * 8) * (KSTRIDE * 2) + c16 * 16);
    const uint32_t v_sm = smem_u32(sVT) + (uint32_t)((li + hi8 * 8) * (VSTRIDE * 2) + c16 * 16);

    // ---- Q fragments for 2 query groups, loaded once ----
    uint32_t qf[2][4];
#pragma unroll
    for (int g = 0; g < 2; g++) {
        const size_t r0 = ((size_t)(bh * T_SZ + q0w + g * 16 + m)) * DH + qc;
        const size_t r1 = r0 + 8 * DH;
        qf[g][0] = *(const uint32_t*)(g_qh + r0);
        qf[g][1] = *(const uint32_t*)(g_qh + r1);
        qf[g][2] = *(const uint32_t*)(g_qh + r0 + 8);
        qf[g][3] = *(const uint32_t*)(g_qh + r1 + 8);
    }

    float Y[2][2][4];
    float L[2][4];
#pragma unroll
    for (int g = 0; g < 2; g++) {
#pragma unroll
        for (int i = 0; i < 4; i++) { Y[g][0][i] = 0.f; Y[g][1][i] = 0.f; L[g][i] = 0.f; }
    }

    const __half* khb = g_kh + (size_t)bh * T_SZ * DH + (size_t)sp * KSPAN * DH;
    const __half* vtb = g_vt + (size_t)bh * DH * T_SZ + sp * KSPAN;

    const int vrow = tid >> 3, vchunk = tid & 7;

    for (int nt = 0; nt < NTS; nt++) {
        const int kt = nt * TK;
        __syncthreads();
        {
            const uint4* sh = (const uint4*)(khb + (size_t)(kt + tid) * DH);
            uint4* dh = (uint4*)(sKh + tid * KSTRIDE);
            dh[0] = sh[0];
            dh[1] = sh[1];
            const uint4* vs = (const uint4*)(vtb + (size_t)vrow * T_SZ + kt + vchunk * 16);
            uint4* vd = (uint4*)(sVT + vrow * VSTRIDE + vchunk * 16);
            vd[0] = vs[0];
            vd[1] = vs[1];
        }
        __syncthreads();

#pragma unroll 2
        for (int st = 0; st < 8; st++) {
            uint32_t b00, b01, b10, b11;
            ldmx4(b00, b01, b10, b11, k_sm + (uint32_t)(st * 16 * KSTRIDE * 2));
            uint32_t vb0, vb1, vc0, vc1;
            ldmx4(vb0, vb1, vc0, vc1, v_sm + (uint32_t)(st * 32));

#pragma unroll
            for (int g = 0; g < 2; g++) {
                float s0[4] = {0.f, 0.f, 0.f, 0.f};
                float s1[4] = {0.f, 0.f, 0.f, 0.f};
                mma16816h(s0, qf[g][0], qf[g][1], qf[g][2], qf[g][3], b00, b01);
                mma16816h(s1, qf[g][0], qf[g][1], qf[g][2], qf[g][3], b10, b11);

                const uint32_t a0 = ex2h2(f16x2_of(s0[0], s0[1]));
                const uint32_t a1 = ex2h2(f16x2_of(s0[2], s0[3]));
                const uint32_t a2 = ex2h2(f16x2_of(s1[0], s1[1]));
                const uint32_t a3 = ex2h2(f16x2_of(s1[2], s1[3]));

                mma16816h(Y[g][0], a0, a1, a2, a3, vb0, vb1);
                mma16816h(Y[g][1], a0, a1, a2, a3, vc0, vc1);
                mma16816h(L[g],    a0, a1, a2, a3, ones, ones);
            }
        }
    }

    // ---- emit unnormalized partials ----
    float* pY = g_pY[sp];
    float* pL = g_pL[sp];
#pragma unroll
    for (int g = 0; g < 2; g++) {
        const size_t r0 = (size_t)(bh * T_SZ + q0w + g * 16 + m);
        const size_t r1 = r0 + 8;
        *(float2*)(pY + r0 * DH + qc)     = make_float2(Y[g][0][0], Y[g][0][1]);
        *(float2*)(pY + r0 * DH + qc + 8) = make_float2(Y[g][1][0], Y[g][1][1]);
        *(float2*)(pY + r1 * DH + qc)     = make_float2(Y[g][0][2], Y[g][0][3]);
        *(float2*)(pY + r1 * DH + qc + 8) = make_float2(Y[g][1][2], Y[g][1][3]);
        if ((lane & 3) == 0) {
            pL[r0] = L[g][0];
            pL[r1] = L[g][2];
        }
    }
}

// ========== Kernel 3: fused split-K merge + output projection ==========
__global__ void __launch_bounds__(256) proj_kernel(
    const float* __restrict__ w, const float* __restrict__ b,
    float* __restrict__ out)
{
    __shared__ ulonglong2 sw2[16 * 64];    // 16KB
    __shared__ ulonglong2 sx2[32 * 16];    // 8KB: y rows packed
    __shared__ float sinv[32][4];
    const int t = threadIdx.x;
    const int row0blk = blockIdx.x * 32;

    const ulonglong2* w2 = (const ulonglong2*)w;
    for (int idx = t; idx < 64 * 16; idx += 256) {
        int c = idx >> 4, k4 = idx & 15;
        sw2[k4 * 64 + c] = w2[idx];
    }

    if (t < 128) {
        const int r  = t >> 2;
        const int h  = t & 3;
        const int row = row0blk + r;
        const int bi = row >> 12, ti = row & 4095;
        const int qi = (bi * H_SZ + h) * T_SZ + ti;
        const float l = g_pL[0][qi] + g_pL[1][qi] + g_pL[2][qi] + g_pL[3][qi];
        sinv[r][h] = 1.0f / l;
    }
    __syncthreads();

    for (int idx = t; idx < 512; idx += 256) {
        const int r  = idx >> 4;
        const int c4 = idx & 15;
        const int row = row0blk + r;
        const int bi = row >> 12, ti = row & 4095;
        const int h  = c4 >> 2;
        const int d4 = c4 & 3;
        const size_t pb = ((size_t)((bi * H_SZ + h) * T_SZ + ti)) * DH + d4 * 4;
        float4 a0 = *(const float4*)(g_pY[0] + pb);
        float4 a1 = *(const float4*)(g_pY[1] + pb);
        float4 a2 = *(const float4*)(g_pY[2] + pb);
        float4 a3 = *(const float4*)(g_pY[3] + pb);
        const float inv = sinv[r][h];
        float4 y;
        y.x = (a0.x + a1.x + a2.x + a3.x) * inv;
        y.y = (a0.y + a1.y + a2.y + a3.y) * inv;
        y.z = (a0.z + a1.z + a2.z + a3.z) * inv;
        y.w = (a0.w + a1.w + a2.w + a3.w) * inv;
        *(float4*)&sx2[r * 16 + c4] = y;
    }
    __syncthreads();

    const int col  = t & 63;
    const int rg   = t >> 6;
    const int row0 = row0blk + rg * 8;
    const float bias = b[col];

    unsigned long long acc2[8];
#pragma unroll
    for (int r = 0; r < 8; r++) acc2[r] = 0ull;

#pragma unroll 4
    for (int k4 = 0; k4 < 16; k4++) {
        const ulonglong2 wv = sw2[k4 * 64 + col];
#pragma unroll
        for (int r = 0; r < 8; r++) {
            const ulonglong2 xv = sx2[(rg * 8 + r) * 16 + k4];
            acc2[r] = fma2(xv.x, wv.x, acc2[r]);
            acc2[r] = fma2(xv.y, wv.y, acc2[r]);
        }
    }

#pragma unroll
    for (int r = 0; r < 8; r++) {
        float lo, hi;
        unpack2(acc2[r], lo, hi);
        out[(row0 + r) * 64 + col] = lo + hi + bias;
    }
}

// ==================== launch ====================
extern "C" void kernel_launch(void* const* d_in, const int* in_sizes, int n_in,
                              void* d_out, int out_size)
{
    const float* x      = (const float*)d_in[0];  // [2,4096,64]
    const float* w_attn = (const float*)d_in[1];  // [192,64]
    const float* b_attn = (const float*)d_in[2];  // [192]
    const float* w_proj = (const float*)d_in[3];  // [64,64]
    const float* b_proj = (const float*)d_in[4];  // [64]
    float* out = (float*)d_out;                   // [2,4096,64]

    qkv_kernel<<<ROWS / 64, 256>>>(x, w_attn, b_attn);

    dim3 ag(T_SZ / QBLK, BH, NSPLIT);   // (32, 8, 4) blocks of 128 threads
    attn_kernel<<<ag, 128>>>();

    proj_kernel<<<ROWS / 32, 256>>>(w_proj, b_proj, out);
}

// round 17
// speedup vs baseline: 9.5404x; 1.0448x over previous
#include <cuda_runtime.h>
#include <cuda_bf16.h>
#include <cuda_fp16.h>
#include <cstdint>

// Problem constants: B=2, T=4096, C=64, H=4, Dh=16
#define B_SZ 2
#define T_SZ 4096
#define C_SZ 64
#define H_SZ 4
#define DH 16
#define BH (B_SZ * H_SZ)          // 8
#define ROWS (B_SZ * T_SZ)        // 8192

// softmax scale (1/sqrt(16)) * log2(e), folded into q before quantization
#define QSCALE 0.360673760222241f

#define TK 128                    // keys per tile
#define QBLK 128                  // queries per block (4 warps x 32)
#define NSPLIT 4
#define KSPAN (T_SZ / NSPLIT)     // 1024 keys per split
#define NTS (KSPAN / TK)          // 8 tiles per split

// smem row strides (fp16 units), conflict-free fragment LDS / LDSM
#define KSTRIDE 24                // 16 data + 8 pad (48B rows)
#define VSTRIDE 136               // 128 data + 8 pad (272B rows)
#define XSTRIDE 72                // 64 data + 8 pad (144B rows)

// -------- scratch (allocation-free rule: __device__ globals) --------
__device__ __align__(32) __half g_qh[BH * T_SZ * DH];  // q*QSCALE (fp16)
__device__ __align__(32) __half g_kh[BH * T_SZ * DH];  // k (fp16)
__device__ __align__(32) __half g_vt[BH * DH * T_SZ];  // v transposed [bh][d][t]
// split-K partials (unnormalized; no max-sub -> combine by pure addition)
__device__ float g_pY[NSPLIT][BH * T_SZ * DH];
__device__ float g_pL[NSPLIT][BH * T_SZ];

// ---------------- fp16 helpers ----------------
__device__ __forceinline__ uint32_t f16x2_of(float lo, float hi) {
    uint32_t r;
    asm("cvt.rn.f16x2.f32 %0, %1, %2;" : "=r"(r) : "f"(hi), "f"(lo));
    return r;
}
__device__ __forceinline__ uint32_t ex2h2(uint32_t s) {
    uint32_t d;
    asm("ex2.approx.f16x2 %0, %1;" : "=r"(d) : "r"(s));
    return d;
}
__device__ __forceinline__ uint32_t smem_u32(const void* p) {
    uint32_t a;
    asm("{ .reg .u64 t; cvta.to.shared.u64 t, %1; cvt.u32.u64 %0, t; }"
        : "=r"(a) : "l"(p));
    return a;
}
// ldmatrix m8n8.x4 (non-trans, b16): 4 fragments in one op
__device__ __forceinline__ void ldmx4(uint32_t& r0, uint32_t& r1,
                                      uint32_t& r2, uint32_t& r3, uint32_t a) {
    asm volatile("ldmatrix.sync.aligned.m8n8.x4.shared.b16 {%0,%1,%2,%3}, [%4];"
                 : "=r"(r0), "=r"(r1), "=r"(r2), "=r"(r3) : "r"(a));
}

// mma.sync m16n8k16 row.col f32.f16.f16.f32, accumulating in place
__device__ __forceinline__ void mma16816h(float c[4],
                                          uint32_t a0, uint32_t a1,
                                          uint32_t a2, uint32_t a3,
                                          uint32_t b0, uint32_t b1) {
    asm("mma.sync.aligned.m16n8k16.row.col.f32.f16.f16.f32 "
        "{%0,%1,%2,%3}, {%4,%5,%6,%7}, {%8,%9}, {%0,%1,%2,%3};"
        : "+f"(c[0]), "+f"(c[1]), "+f"(c[2]), "+f"(c[3])
        : "r"(a0), "r"(a1), "r"(a2), "r"(a3), "r"(b0), "r"(b1));
}

// ==================== Kernel 1: tensor-core QKV projection ==============
// Grid 256 blocks x 128 threads (4 warps). Block = 32 rows x 192 cols, K=64.
// Warp = 16-row group x 96-col half. x/w converted fp32->fp16 into
// ldmatrix-friendly smem; epilogue scatters fragments into q/k/vt.
__global__ void __launch_bounds__(128) qkv_kernel(
    const float* __restrict__ x, const float* __restrict__ w,
    const float* __restrict__ b)
{
    __shared__ __half sX[32 * XSTRIDE];    // 4.6 KB
    __shared__ __half sW[192 * XSTRIDE];   // 27.6 KB
    __shared__ float sB[192];
    const int t = threadIdx.x;

    // stage W (convert fp32 -> fp16)
    const float4* w4 = (const float4*)w;          // w4[n*16 + k4]
    for (int idx = t; idx < 192 * 16; idx += 128) {
        const int n = idx >> 4, k4 = idx & 15;
        const float4 f = w4[idx];
        uint2 h;
        h.x = f16x2_of(f.x, f.y);
        h.y = f16x2_of(f.z, f.w);
        *(uint2*)(sW + n * XSTRIDE + k4 * 4) = h;
    }
    // stage X (convert fp32 -> fp16)
    const float4* x4 = (const float4*)x + (size_t)blockIdx.x * 32 * 16;
    for (int idx = t; idx < 32 * 16; idx += 128) {
        const int r = idx >> 4, k4 = idx & 15;
        const float4 f = x4[idx];
        uint2 h;
        h.x = f16x2_of(f.x, f.y);
        h.y = f16x2_of(f.z, f.w);
        *(uint2*)(sX + r * XSTRIDE + k4 * 4) = h;
    }
    for (int idx = t; idx < 192; idx += 128) sB[idx] = b[idx];
    __syncthreads();

    const int warp = t >> 5, lane = t & 31;
    const int rg     = warp >> 1;      // row group 0..1 (16 rows each)
    const int chalfw = warp & 1;       // col half: 0 -> cols 0-95, 1 -> 96-191
    const int m_ = lane >> 2;          // 0..7
    const int qc = (lane & 3) * 2;     // 0,2,4,6
    const int li = lane & 7;
    const int c16 = (lane >> 3) & 1;
    const int hi8 = (lane >> 4) & 1;

    // A fragments: rows rg*16..+15, k=0..63 (4 ksteps)
    uint32_t a[4][4];
    {
        const uint32_t xa = smem_u32(sX)
            + (uint32_t)(((rg * 16 + li + hi8 * 8) * XSTRIDE + c16 * 8) * 2);
#pragma unroll
        for (int ks = 0; ks < 4; ks++) {
            uint32_t r0, r1, r2, r3;
            ldmx4(r0, r1, r2, r3, xa + ks * 32);
            a[ks][0] = r0; a[ks][1] = r2; a[ks][2] = r1; a[ks][3] = r3;
        }
    }

    const uint32_t wb = smem_u32(sW) + (uint32_t)(((li + hi8 * 8) * XSTRIDE + c16 * 8) * 2);
    const int row0 = blockIdx.x * 32 + rg * 16;
    const int bi   = row0 >> 12;
    const int ti0  = (row0 & 4095) + m_;

#pragma unroll
    for (int p = 0; p < 6; p++) {
        const int n0 = chalfw * 96 + p * 16;    // two n-tiles: n0, n0+8
        float c0[4] = {0.f, 0.f, 0.f, 0.f};
        float c1[4] = {0.f, 0.f, 0.f, 0.f};
#pragma unroll
        for (int ks = 0; ks < 4; ks++) {
            uint32_t b0, b1, b2, b3;
            ldmx4(b0, b1, b2, b3, wb + (uint32_t)(n0 * XSTRIDE * 2 + ks * 32));
            mma16816h(c0, a[ks][0], a[ks][1], a[ks][2], a[ks][3], b0, b1);
            mma16816h(c1, a[ks][0], a[ks][1], a[ks][2], a[ks][3], b2, b3);
        }
        // epilogue: two n-tiles
#pragma unroll
        for (int sub = 0; sub < 2; sub++) {
            float* c = sub ? c1 : c0;
            const int col0 = n0 + sub * 8;
            const float b0v = sB[col0 + qc];
            const float b1v = sB[col0 + qc + 1];
            float e0 = c[0] + b0v, e1 = c[1] + b1v;
            float e2 = c[2] + b0v, e3 = c[3] + b1v;
            const int seg = col0 >> 6;          // 0=q, 1=k, 2=v
            const int cc  = col0 & 63;
            const int h   = cc >> 4;
            const int d0  = (cc & 15) + qc;
            const int bh  = bi * H_SZ + h;
            if (seg == 0) {
                e0 *= QSCALE; e1 *= QSCALE; e2 *= QSCALE; e3 *= QSCALE;
                const size_t base = ((size_t)(bh * T_SZ + ti0)) * DH + d0;
                *(uint32_t*)(g_qh + base)          = f16x2_of(e0, e1);
                *(uint32_t*)(g_qh + base + 8 * DH) = f16x2_of(e2, e3);
            } else if (seg == 1) {
                const size_t base = ((size_t)(bh * T_SZ + ti0)) * DH + d0;
                *(uint32_t*)(g_kh + base)          = f16x2_of(e0, e1);
                *(uint32_t*)(g_kh + base + 8 * DH) = f16x2_of(e2, e3);
            } else {
                const size_t vb = ((size_t)(bh * DH + d0)) * T_SZ + ti0;
                g_vt[vb]            = __float2half(e0);
                g_vt[vb + T_SZ]     = __float2half(e1);
                g_vt[vb + 8]        = __float2half(e2);
                g_vt[vb + T_SZ + 8] = __float2half(e3);
            }
        }
    }
}

// ============== Kernel 2: fp16 mma.sync flash attention (split-K) =======
// Grid (T/128, BH, NSPLIT), 128 threads (4 warps x 32 queries).
// K/V fragments via ldmatrix.x4; S = Q*K (fp32 acc); p = ex2.f16x2(S) ->
// PV A-fragment directly. Row sums via HADD2+cvt on the FMA pipe (tensor
// pipe saved for S/Y). Emits unnormalized partials (pure-add merge in proj).
__global__ void __launch_bounds__(128) attn_kernel()
{
    __shared__ __half sKh[TK * KSTRIDE];   // 6 KB
    __shared__ __half sVT[DH * VSTRIDE];   // 4.25 KB

    const int tid  = threadIdx.x;
    const int warp = tid >> 5;
    const int lane = tid & 31;
    const int bh   = blockIdx.y;
    const int sp   = blockIdx.z;
    const int q0w  = blockIdx.x * QBLK + warp * 32;
    const int m    = lane >> 2;        // 0..7 (row group)
    const int qc   = (lane & 3) * 2;   // 0,2,4,6 (col pair)

    // ldmatrix per-thread source addresses (4 matrices per op)
    const int li = lane & 7;
    const int hi8  = (lane >> 4) & 1;
    const int c16  = (lane >> 3) & 1;
    const uint32_t k_sm = smem_u32(sKh) + (uint32_t)((li + hi8 * 8) * (KSTRIDE * 2) + c16 * 16);
    const uint32_t v_sm = smem_u32(sVT) + (uint32_t)((li + hi8 * 8) * (VSTRIDE * 2) + c16 * 16);

    // ---- Q fragments for 2 query groups, loaded once ----
    uint32_t qf[2][4];
#pragma unroll
    for (int g = 0; g < 2; g++) {
        const size_t r0 = ((size_t)(bh * T_SZ + q0w + g * 16 + m)) * DH + qc;
        const size_t r1 = r0 + 8 * DH;
        qf[g][0] = *(const uint32_t*)(g_qh + r0);
        qf[g][1] = *(const uint32_t*)(g_qh + r1);
        qf[g][2] = *(const uint32_t*)(g_qh + r0 + 8);
        qf[g][3] = *(const uint32_t*)(g_qh + r1 + 8);
    }

    float Y[2][2][4];
    float lsum[2][2] = {{0.f, 0.f}, {0.f, 0.f}};   // [qgroup][row-half]
#pragma unroll
    for (int g = 0; g < 2; g++)
#pragma unroll
        for (int i = 0; i < 4; i++) { Y[g][0][i] = 0.f; Y[g][1][i] = 0.f; }

    const __half* khb = g_kh + (size_t)bh * T_SZ * DH + (size_t)sp * KSPAN * DH;
    const __half* vtb = g_vt + (size_t)bh * DH * T_SZ + sp * KSPAN;

    const int vrow = tid >> 3, vchunk = tid & 7;

    for (int nt = 0; nt < NTS; nt++) {
        const int kt = nt * TK;
        __syncthreads();
        {
            const uint4* sh = (const uint4*)(khb + (size_t)(kt + tid) * DH);
            uint4* dh = (uint4*)(sKh + tid * KSTRIDE);
            dh[0] = sh[0];
            dh[1] = sh[1];
            const uint4* vs = (const uint4*)(vtb + (size_t)vrow * T_SZ + kt + vchunk * 16);
            uint4* vd = (uint4*)(sVT + vrow * VSTRIDE + vchunk * 16);
            vd[0] = vs[0];
            vd[1] = vs[1];
        }
        __syncthreads();

#pragma unroll 2
        for (int st = 0; st < 8; st++) {
            uint32_t b00, b01, b10, b11;
            ldmx4(b00, b01, b10, b11, k_sm + (uint32_t)(st * 16 * KSTRIDE * 2));
            uint32_t vb0, vb1, vc0, vc1;
            ldmx4(vb0, vb1, vc0, vc1, v_sm + (uint32_t)(st * 32));

#pragma unroll
            for (int g = 0; g < 2; g++) {
                float s0[4] = {0.f, 0.f, 0.f, 0.f};
                float s1[4] = {0.f, 0.f, 0.f, 0.f};
                mma16816h(s0, qf[g][0], qf[g][1], qf[g][2], qf[g][3], b00, b01);
                mma16816h(s1, qf[g][0], qf[g][1], qf[g][2], qf[g][3], b10, b11);

                uint32_t a0 = ex2h2(f16x2_of(s0[0], s0[1]));
                uint32_t a1 = ex2h2(f16x2_of(s0[2], s0[3]));
                uint32_t a2 = ex2h2(f16x2_of(s1[0], s1[1]));
                uint32_t a3 = ex2h2(f16x2_of(s1[2], s1[3]));

                mma16816h(Y[g][0], a0, a1, a2, a3, vb0, vb1);
                mma16816h(Y[g][1], a0, a1, a2, a3, vc0, vc1);

                // row sums on the FMA pipe (tensor pipe is the bottleneck)
                const __half2 s01 = __hadd2(*(__half2*)&a0, *(__half2*)&a2); // row m
                const __half2 s23 = __hadd2(*(__half2*)&a1, *(__half2*)&a3); // row m+8
                const float2 f0 = __half22float2(s01);
                const float2 f1 = __half22float2(s23);
                lsum[g][0] += f0.x + f0.y;
                lsum[g][1] += f1.x + f1.y;
            }
        }
    }

    // ---- quad-reduce row sums; emit unnormalized partials ----
    float* pY = g_pY[sp];
    float* pL = g_pL[sp];
#pragma unroll
    for (int g = 0; g < 2; g++) {
        float l0 = lsum[g][0], l1 = lsum[g][1];
        l0 += __shfl_xor_sync(0xffffffffu, l0, 1);
        l0 += __shfl_xor_sync(0xffffffffu, l0, 2);
        l1 += __shfl_xor_sync(0xffffffffu, l1, 1);
        l1 += __shfl_xor_sync(0xffffffffu, l1, 2);

        const size_t r0 = (size_t)(bh * T_SZ + q0w + g * 16 + m);
        const size_t r1 = r0 + 8;
        *(float2*)(pY + r0 * DH + qc)     = make_float2(Y[g][0][0], Y[g][0][1]);
        *(float2*)(pY + r0 * DH + qc + 8) = make_float2(Y[g][1][0], Y[g][1][1]);
        *(float2*)(pY + r1 * DH + qc)     = make_float2(Y[g][0][2], Y[g][0][3]);
        *(float2*)(pY + r1 * DH + qc + 8) = make_float2(Y[g][1][2], Y[g][1][3]);
        if ((lane & 3) == 0) {
            pL[r0] = l0;
            pL[r1] = l1;
        }
    }
}

// ====== Kernel 3: fused split-K merge + tensor-core output projection ===
// Grid 256 blocks x 128 threads (4 warps). Block = 32 rows x 64 cols, K=64.
// Stage 1: sum 4 partials + normalize -> fp16 smem. Stage 2: mma GEMM.
__global__ void __launch_bounds__(128) proj_kernel(
    const float* __restrict__ w, const float* __restrict__ b,
    float* __restrict__ out)
{
    __shared__ __half sW[64 * XSTRIDE];    // 9.2 KB
    __shared__ __half sY[32 * XSTRIDE];    // 4.6 KB
    __shared__ float sB[64];
    __shared__ float sinv[32][4];
    const int t = threadIdx.x;
    const int row0blk = blockIdx.x * 32;

    // stage W (convert fp32 -> fp16); rows = output col n, cols = k
    const float4* w4 = (const float4*)w;
    for (int idx = t; idx < 64 * 16; idx += 128) {
        const int n = idx >> 4, k4 = idx & 15;
        const float4 f = w4[idx];
        uint2 h;
        h.x = f16x2_of(f.x, f.y);
        h.y = f16x2_of(f.z, f.w);
        *(uint2*)(sW + n * XSTRIDE + k4 * 4) = h;
    }
    if (t < 64) sB[t] = b[t];
    // per-(row, head) inverse row sums
    {
        const int r  = t >> 2;
        const int h  = t & 3;
        const int row = row0blk + r;
        const int bi = row >> 12, ti = row & 4095;
        const int qi = (bi * H_SZ + h) * T_SZ + ti;
        sinv[r][h] = 1.0f / (g_pL[0][qi] + g_pL[1][qi] + g_pL[2][qi] + g_pL[3][qi]);
    }
    __syncthreads();

    // merge partials + normalize into fp16 sY (32 rows x 64 k)
    for (int idx = t; idx < 512; idx += 128) {
        const int r  = idx >> 4;
        const int c4 = idx & 15;
        const int row = row0blk + r;
        const int bi = row >> 12, ti = row & 4095;
        const int h  = c4 >> 2;
        const int d4 = c4 & 3;
        const size_t pb = ((size_t)((bi * H_SZ + h) * T_SZ + ti)) * DH + d4 * 4;
        float4 a0 = *(const float4*)(g_pY[0] + pb);
        float4 a1 = *(const float4*)(g_pY[1] + pb);
        float4 a2 = *(const float4*)(g_pY[2] + pb);
        float4 a3 = *(const float4*)(g_pY[3] + pb);
        const float inv = sinv[r][h];
        uint2 hh;
        hh.x = f16x2_of((a0.x + a1.x + a2.x + a3.x) * inv,
                        (a0.y + a1.y + a2.y + a3.y) * inv);
        hh.y = f16x2_of((a0.z + a1.z + a2.z + a3.z) * inv,
                        (a0.w + a1.w + a2.w + a3.w) * inv);
        *(uint2*)(sY + r * XSTRIDE + c4 * 4) = hh;
    }
    __syncthreads();

    const int warp = t >> 5, lane = t & 31;
    const int rg = warp >> 1;          // 16-row group
    const int ch = warp & 1;           // 32-col half
    const int m_ = lane >> 2;
    const int qc = (lane & 3) * 2;
    const int li = lane & 7;
    const int c16 = (lane >> 3) & 1;
    const int hi8 = (lane >> 4) & 1;

    uint32_t a[4][4];
    {
        const uint32_t ya = smem_u32(sY)
            + (uint32_t)(((rg * 16 + li + hi8 * 8) * XSTRIDE + c16 * 8) * 2);
#pragma unroll
        for (int ks = 0; ks < 4; ks++) {
            uint32_t r0, r1, r2, r3;
            ldmx4(r0, r1, r2, r3, ya + ks * 32);
            a[ks][0] = r0; a[ks][1] = r2; a[ks][2] = r1; a[ks][3] = r3;
        }
    }

    const uint32_t wb = smem_u32(sW) + (uint32_t)(((li + hi8 * 8) * XSTRIDE + c16 * 8) * 2);
    const int row0 = row0blk + rg * 16;

#pragma unroll
    for (int p = 0; p < 2; p++) {
        const int n0 = ch * 32 + p * 16;
        float c0[4] = {0.f, 0.f, 0.f, 0.f};
        float c1[4] = {0.f, 0.f, 0.f, 0.f};
#pragma unroll
        for (int ks = 0; ks < 4; ks++) {
            uint32_t b0, b1, b2, b3;
            ldmx4(b0, b1, b2, b3, wb + (uint32_t)(n0 * XSTRIDE * 2 + ks * 32));
            mma16816h(c0, a[ks][0], a[ks][1], a[ks][2], a[ks][3], b0, b1);
            mma16816h(c1, a[ks][0], a[ks][1], a[ks][2], a[ks][3], b2, b3);
        }
#pragma unroll
        for (int sub = 0; sub < 2; sub++) {
            float* c = sub ? c1 : c0;
            const int col0 = n0 + sub * 8;
            const float b0v = sB[col0 + qc];
            const float b1v = sB[col0 + qc + 1];
            float* o0 = out + (size_t)(row0 + m_) * C_SZ + col0 + qc;
            float* o1 = o0 + 8 * C_SZ;
            *(float2*)o0 = make_float2(c[0] + b0v, c[1] + b1v);
            *(float2*)o1 = make_float2(c[2] + b0v, c[3] + b1v);
        }
    }
}

// ==================== launch ====================
extern "C" void kernel_launch(void* const* d_in, const int* in_sizes, int n_in,
                              void* d_out, int out_size)
{
    const float* x      = (const float*)d_in[0];  // [2,4096,64]
    const float* w_attn = (const float*)d_in[1];  // [192,64]
    const float* b_attn = (const float*)d_in[2];  // [192]
    const float* w_proj = (const float*)d_in[3];  // [64,64]
    const float* b_proj = (const float*)d_in[4];  // [64]
    float* out = (float*)d_out;                   // [2,4096,64]

    qkv_kernel<<<ROWS / 32, 128>>>(x, w_attn, b_attn);

    dim3 ag(T_SZ / QBLK, BH, NSPLIT);   // (32, 8, 4) blocks of 128 threads
    attn_kernel<<<ag, 128>>>();

    proj_kernel<<<ROWS / 32, 128>>>(w_proj, b_proj, out);
}